// round 5
// baseline (speedup 1.0000x reference)
#include <cuda_runtime.h>
#include <cstdint>
#include <cstddef>

#define DEV static __device__ __forceinline__
typedef unsigned long long u64;

constexpr int Bb = 16, Ll = 8192;
constexpr int CH = 8;                 // L-chunks in phase 1
constexpr int NSUB = (Ll / CH) / 128; // 8 subtiles of 128 per chunk
constexpr float SCALE = 0.08838834764831845f; // 1/sqrt(128)

// ---------------- scratch (device globals; no allocation) ----------------
__device__ float g_VT[(size_t)Bb * Ll * 128];     // V transposed: [b][l][v]
__device__ float g_kvpart[Bb * CH * 128 * 128];   // kv partials
__device__ float g_kspart[Bb * CH * 128];         // ksum partials
__device__ float g_kv[Bb * 128 * 128];            // kv final: [b][m][v]
__device__ float g_ksum[Bb * 128];                // ksum final

// ---------------- packed f32x2 helpers ----------------
DEV u64 pk2(float lo, float hi) { u64 r; asm("mov.b64 %0,{%1,%2};" : "=l"(r) : "f"(lo), "f"(hi)); return r; }
DEV float2 upk2(u64 v) { float2 r; asm("mov.b64 {%0,%1},%2;" : "=f"(r.x), "=f"(r.y) : "l"(v)); return r; }
DEV void fma2(u64 &d, u64 a, u64 b) { asm("fma.rn.f32x2 %0,%1,%2,%0;" : "+l"(d) : "l"(a), "l"(b)); }
DEV float rcp_nr(float x) { float r; asm("rcp.approx.f32 %0,%1;" : "=f"(r) : "f"(x)); return r * (2.0f - x * r); }

// ---------------- cp.async helpers ----------------
DEV void cp16(uint32_t s, const void *g) { asm volatile("cp.async.ca.shared.global [%0],[%1],16;" :: "r"(s), "l"(g)); }
DEV void cpcommit() { asm volatile("cp.async.commit_group;"); }
DEV void cpwait() { asm volatile("cp.async.wait_group 0;"); }

// Load a 128x128 fp32 tile (row-major, row stride gstride floats) into smem
// with a permuted 16B-unit layout: 16B chunk c4 of a row goes to unit
// ((c4&1)<<4)|(c4>>1). Fragment reads then touch 16 consecutive units ->
// all 8 bank quads -> 4-phase (minimum) conflict-free LDS.128.
DEV void load_tile(uint32_t sb, const float *g, int gstride) {
    int t = threadIdx.x, c4 = t & 31, r0 = t >> 5;
    uint32_t ub = (uint32_t)((((c4 & 1) << 4) | (c4 >> 1)) * 16); // unit byte offset
#pragma unroll
    for (int i = 0; i < 16; i++) {
        int row = i * 8 + r0;
        cp16(sb + (uint32_t)row * 512u + ub, g + (size_t)row * gstride + c4 * 4);
    }
}

// ---------------- 128x128x128 SIMT GEMM core (8x8 microtile, f32x2) ----------
// C[8ty+i][8tx+{2j,2j+1}] += sum_r A[r][8ty+i] * B[r][8tx+...]
// A-frag: units ty, 16+ty (2 distinct/warp -> broadcast); B-frag: units tx, 16+tx.
template <bool KSUM, bool DEN>
DEV void mm128(const float4 *A4, const float4 *B4, int ty, int tx,
               u64 (*c)[4], float *ksum, const float *ksv, u64 *dnm) {
#pragma unroll 4
    for (int r = 0; r < 128; r++) {
        float4 a0 = A4[r * 32 + ty], a1 = A4[r * 32 + 16 + ty];
        float4 b0 = B4[r * 32 + tx], b1 = B4[r * 32 + 16 + tx];
        u64 bp0 = pk2(b0.x, b0.y), bp1 = pk2(b0.z, b0.w);
        u64 bp2 = pk2(b1.x, b1.y), bp3 = pk2(b1.z, b1.w);
        float av[8] = {a0.x, a0.y, a0.z, a0.w, a1.x, a1.y, a1.z, a1.w};
#pragma unroll
        for (int i = 0; i < 8; i++) {
            u64 ad = pk2(av[i], av[i]);
            fma2(c[i][0], ad, bp0); fma2(c[i][1], ad, bp1);
            fma2(c[i][2], ad, bp2); fma2(c[i][3], ad, bp3);
            if (KSUM) ksum[i] += av[i];
        }
        if (DEN) {
            u64 kd = pk2(ksv[r], ksv[r]);
            fma2(dnm[0], kd, bp0); fma2(dnm[1], kd, bp1);
            fma2(dnm[2], kd, bp2); fma2(dnm[3], kd, bp3);
        }
    }
}

// ---------------- Kernel T: V[b][v][l] -> VT[b][l][v] ----------------
__global__ __launch_bounds__(256, 1) void k_trans(const float *__restrict__ V) {
    extern __shared__ float ts[]; // 16384 floats, XOR-swizzled: word(v,l)=v*128+(l^(v>>2))
    int b = blockIdx.y, l0 = blockIdx.x * 128, t = threadIdx.x;
    int c4 = t & 31, r0 = t >> 5;
#pragma unroll
    for (int i = 0; i < 16; i++) {
        int v = i * 8 + r0, lb = c4 * 4;
        float4 g = *(const float4 *)(V + ((size_t)(b * 128 + v)) * Ll + l0 + lb);
        int s = v >> 2;
        ts[v * 128 + ((lb + 0) ^ s)] = g.x;
        ts[v * 128 + ((lb + 1) ^ s)] = g.y;
        ts[v * 128 + ((lb + 2) ^ s)] = g.z;
        ts[v * 128 + ((lb + 3) ^ s)] = g.w;
    }
    __syncthreads();
#pragma unroll
    for (int i = 0; i < 16; i++) {
        int l = i * 8 + r0, vb = (t & 31) * 4;
        float4 o; // (vb+k)>>2 == c4 for k<4 -> same xor as writes; reads conflict-free
        o.x = ts[(vb + 0) * 128 + (l ^ c4)];
        o.y = ts[(vb + 1) * 128 + (l ^ c4)];
        o.z = ts[(vb + 2) * 128 + (l ^ c4)];
        o.w = ts[(vb + 3) * 128 + (l ^ c4)];
        *(float4 *)(g_VT + ((size_t)b * Ll + l0 + l) * 128 + vb) = o;
    }
}

// ---------------- Kernel P1: phi_k + kv/ksum partials ----------------
__global__ __launch_bounds__(256, 1) void k_p1(const float *__restrict__ keys,
                                               const float *__restrict__ feats) {
    extern __shared__ float smem[];
    uint32_t sb = (uint32_t)__cvta_generic_to_shared(smem);
    const float4 *W4 = (const float4 *)smem;
    const float4 *Bf4 = (const float4 *)(smem + 16384);
    const float4 *Ph4 = (const float4 *)(smem + 32768);
    float4 *PhW = (float4 *)(smem + 32768);
    int b = blockIdx.y, ch = blockIdx.x, t = threadIdx.x;
    int ty = t >> 4, tx = t & 15;

    load_tile(sb, feats, 128); // W[d][m], natural layout
    cpcommit();

    u64 c2[8][4]; float ksm[8];
#pragma unroll
    for (int i = 0; i < 8; i++) {
        ksm[i] = 0.f;
#pragma unroll
        for (int j = 0; j < 4; j++) c2[i][j] = 0ull;
    }

    for (int st = 0; st < NSUB; st++) {
        int l0 = ch * (Ll / CH) + st * 128;
        __syncthreads(); // previous GEMM2 done with buf
        load_tile(sb + 65536, keys + (size_t)b * 128 * Ll + l0, Ll); // K[d][l]
        cpcommit(); cpwait(); __syncthreads();

        u64 p[8][4];
#pragma unroll
        for (int i = 0; i < 8; i++)
#pragma unroll
            for (int j = 0; j < 4; j++) p[i][j] = 0ull;

        // GEMM1: phi[l][m] = relu(K^T W)*s : A = K tile (ty = l), B = W (tx = m)
        mm128<false, false>(Bf4, W4, ty, tx, p, nullptr, nullptr, nullptr);

#pragma unroll
        for (int i = 0; i < 8; i++) {
            float v[8];
#pragma unroll
            for (int j = 0; j < 4; j++) {
                float2 f = upk2(p[i][j]);
                v[2 * j] = fmaxf(f.x * SCALE, 0.f);
                v[2 * j + 1] = fmaxf(f.y * SCALE, 0.f);
            }
            int row = ty * 8 + i; // l-local
            PhW[row * 32 + tx] = make_float4(v[0], v[1], v[2], v[3]);
            PhW[row * 32 + 16 + tx] = make_float4(v[4], v[5], v[6], v[7]);
        }
        __syncthreads(); // phi written; K reads done -> buf reusable
        load_tile(sb + 65536, g_VT + ((size_t)b * Ll + l0) * 128, 128); // VT[l][v]
        cpcommit(); cpwait(); __syncthreads();

        // GEMM2: kv[m][v] += phi^T ... A = phi[l][m-frag] (ty=m), B = VT[l][v-frag] (tx=v)
        mm128<true, false>(Ph4, Bf4, ty, tx, c2, ksm, nullptr, nullptr);
    }

    float *kvp = g_kvpart + (size_t)(b * CH + ch) * 16384;
#pragma unroll
    for (int i = 0; i < 8; i++) {
        float2 f0 = upk2(c2[i][0]), f1 = upk2(c2[i][1]);
        float2 f2 = upk2(c2[i][2]), f3 = upk2(c2[i][3]);
        float4 *dst = (float4 *)(kvp + (ty * 8 + i) * 128 + tx * 8);
        dst[0] = make_float4(f0.x, f0.y, f1.x, f1.y);
        dst[1] = make_float4(f2.x, f2.y, f3.x, f3.y);
    }
    if (tx == 0) {
#pragma unroll
        for (int i = 0; i < 8; i++)
            g_kspart[(b * CH + ch) * 128 + ty * 8 + i] = ksm[i];
    }
}

// ---------------- Kernel R: reduce partials ----------------
__global__ __launch_bounds__(256) void k_red() {
    int b = blockIdx.x >> 4, sl = blockIdx.x & 15, t = threadIdx.x;
    int e = sl * 1024 + t * 4;
    float4 acc = make_float4(0.f, 0.f, 0.f, 0.f);
#pragma unroll
    for (int ch = 0; ch < CH; ch++) {
        float4 v = *(const float4 *)(g_kvpart + (size_t)(b * CH + ch) * 16384 + e);
        acc.x += v.x; acc.y += v.y; acc.z += v.z; acc.w += v.w;
    }
    *(float4 *)(g_kv + (size_t)b * 16384 + e) = acc;
    if (sl == 0 && t < 128) {
        float s = 0.f;
#pragma unroll
        for (int ch = 0; ch < CH; ch++) s += g_kspart[(b * CH + ch) * 128 + t];
        g_ksum[b * 128 + t] = s;
    }
}

// ---------------- Kernel P2: phi_q + out ----------------
__global__ __launch_bounds__(256, 1) void k_p2(const float *__restrict__ queries,
                                               const float *__restrict__ feats,
                                               float *__restrict__ out) {
    extern __shared__ float smem[];
    uint32_t sb = (uint32_t)__cvta_generic_to_shared(smem);
    const float4 *W4 = (const float4 *)smem;
    const float4 *Bf4 = (const float4 *)(smem + 16384);
    const float4 *Ph4 = (const float4 *)(smem + 32768);
    float4 *PhW = (float4 *)(smem + 32768);
    const float *Ks = smem + 49152;
    int b = blockIdx.y, l0 = blockIdx.x * 128, t = threadIdx.x;
    int ty = t >> 4, tx = t & 15;

    load_tile(sb, feats, 128);
    load_tile(sb + 65536, queries + (size_t)b * 128 * Ll + l0, Ll);
    cpcommit(); cpwait(); __syncthreads();

    u64 p[8][4];
#pragma unroll
    for (int i = 0; i < 8; i++)
#pragma unroll
        for (int j = 0; j < 4; j++) p[i][j] = 0ull;

    // GEMM1: phi_q[m][l] : A = W (ty = m), B = Q tile (tx = l)
    mm128<false, false>(W4, Bf4, ty, tx, p, nullptr, nullptr, nullptr);

#pragma unroll
    for (int i = 0; i < 8; i++) {
        float v[8];
#pragma unroll
        for (int j = 0; j < 4; j++) {
            float2 f = upk2(p[i][j]);
            v[2 * j] = fmaxf(f.x * SCALE, 0.f);
            v[2 * j + 1] = fmaxf(f.y * SCALE, 0.f);
        }
        int row = ty * 8 + i; // m
        PhW[row * 32 + tx] = make_float4(v[0], v[1], v[2], v[3]);
        PhW[row * 32 + 16 + tx] = make_float4(v[4], v[5], v[6], v[7]);
    }
    __syncthreads();
    load_tile(sb + 65536, g_kv + (size_t)b * 16384, 128); // kv[m][v]
    if (t < 32) cp16(sb + 196608 + (uint32_t)t * 16, g_ksum + b * 128 + t * 4);
    cpcommit(); cpwait(); __syncthreads();

    u64 c2[8][4], dnm[4];
#pragma unroll
    for (int j = 0; j < 4; j++) dnm[j] = 0ull;
#pragma unroll
    for (int i = 0; i < 8; i++)
#pragma unroll
        for (int j = 0; j < 4; j++) c2[i][j] = 0ull;

    // GEMM2: out[v][l] = sum_m kv[m][v]*phi_q[m][l]; denom folded via ksum
    mm128<false, true>(Bf4, Ph4, ty, tx, c2, nullptr, Ks, dnm);

    float rl[8];
#pragma unroll
    for (int j = 0; j < 4; j++) {
        float2 d = upk2(dnm[j]);
        rl[2 * j] = rcp_nr(d.x);
        rl[2 * j + 1] = rcp_nr(d.y);
    }
#pragma unroll
    for (int i = 0; i < 8; i++) {
        float2 f0 = upk2(c2[i][0]), f1 = upk2(c2[i][1]);
        float2 f2 = upk2(c2[i][2]), f3 = upk2(c2[i][3]);
        float4 *dst = (float4 *)(out + ((size_t)(b * 128 + ty * 8 + i)) * Ll + l0 + tx * 8);
        dst[0] = make_float4(f0.x * rl[0], f0.y * rl[1], f1.x * rl[2], f1.y * rl[3]);
        dst[1] = make_float4(f2.x * rl[4], f2.y * rl[5], f3.x * rl[6], f3.y * rl[7]);
    }
}

// ---------------- launch ----------------
extern "C" void kernel_launch(void *const *d_in, const int *in_sizes, int n_in,
                              void *d_out, int out_size) {
    (void)in_sizes; (void)n_in; (void)out_size;
    const float *keys = (const float *)d_in[0];
    const float *values = (const float *)d_in[1];
    const float *queries = (const float *)d_in[2];
    const float *feats = (const float *)d_in[3];
    float *out = (float *)d_out;

    cudaFuncSetAttribute(k_trans, cudaFuncAttributeMaxDynamicSharedMemorySize, 65536);
    cudaFuncSetAttribute(k_p1, cudaFuncAttributeMaxDynamicSharedMemorySize, 197120);
    cudaFuncSetAttribute(k_p2, cudaFuncAttributeMaxDynamicSharedMemorySize, 197120);

    dim3 gt(Ll / 128, Bb);
    k_trans<<<gt, 256, 65536>>>(values);
    dim3 g1(CH, Bb);
    k_p1<<<g1, 256, 197120>>>(keys, feats);
    k_red<<<256, 256>>>();
    dim3 g2(Ll / 128, Bb);
    k_p2<<<g2, 256, 197120>>>(queries, feats, out);
}

// round 6
// speedup vs baseline: 1.0025x; 1.0025x over previous
#include <cuda_runtime.h>
#include <cstdint>
#include <cstddef>

#define DEV static __device__ __forceinline__
typedef unsigned long long u64;

constexpr int Bb = 16, Ll = 8192;
constexpr int CH = 8;                 // L-chunks in phase 1
constexpr int NSUB = (Ll / CH) / 128; // 8 subtiles of 128 per chunk
constexpr float SCALE = 0.08838834764831845f; // 1/sqrt(128)

// ---------------- scratch (device globals; no allocation) ----------------
__device__ float g_VT[(size_t)Bb * Ll * 128];     // V transposed: [b][l][v]
__device__ float g_kvpart[Bb * CH * 128 * 128];   // kv partials
__device__ float g_kspart[Bb * CH * 128];         // ksum partials
__device__ float g_kv[Bb * 128 * 128];            // kv final: [b][m][v]
__device__ float g_ksum[Bb * 128];                // ksum final

// ---------------- packed f32x2 helpers ----------------
DEV u64 pk2(float lo, float hi) { u64 r; asm("mov.b64 %0,{%1,%2};" : "=l"(r) : "f"(lo), "f"(hi)); return r; }
DEV float2 upk2(u64 v) { float2 r; asm("mov.b64 {%0,%1},%2;" : "=f"(r.x), "=f"(r.y) : "l"(v)); return r; }
DEV void fma2(u64 &d, u64 a, u64 b) { asm("fma.rn.f32x2 %0,%1,%2,%0;" : "+l"(d) : "l"(a), "l"(b)); }
DEV float rcp_nr(float x) { float r; asm("rcp.approx.f32 %0,%1;" : "=f"(r) : "f"(x)); return r * (2.0f - x * r); }

// ---------------- cp.async helpers ----------------
DEV void cp16(uint32_t s, const void *g) { asm volatile("cp.async.ca.shared.global [%0],[%1],16;" :: "r"(s), "l"(g)); }
DEV void cpcommit() { asm volatile("cp.async.commit_group;"); }
DEV void cpwait() { asm volatile("cp.async.wait_group 0;"); }

// Load a 128x128 fp32 tile (row-major, row stride gstride floats) into smem
// with a permuted 16B-unit layout: 16B chunk c4 of a row goes to unit
// ((c4&1)<<4)|(c4>>1). Fragment reads then touch 16 consecutive units ->
// all 8 bank quads -> 4-phase (minimum) conflict-free LDS.128.
DEV void load_tile(uint32_t sb, const float *g, int gstride) {
    int t = threadIdx.x, c4 = t & 31, r0 = t >> 5;
    uint32_t ub = (uint32_t)((((c4 & 1) << 4) | (c4 >> 1)) * 16); // unit byte offset
#pragma unroll
    for (int i = 0; i < 16; i++) {
        int row = i * 8 + r0;
        cp16(sb + (uint32_t)row * 512u + ub, g + (size_t)row * gstride + c4 * 4);
    }
}

// ---------------- 128x128x128 SIMT GEMM core (8x8 microtile, f32x2) ----------
// C[8ty+i][8tx+{2j,2j+1}] += sum_r A[r][8ty+i] * B[r][8tx+...]
// A-frag: units ty, 16+ty (2 distinct/warp -> broadcast); B-frag: units tx, 16+tx.
template <bool KSUM, bool DEN>
DEV void mm128(const float4 *A4, const float4 *B4, int ty, int tx,
               u64 (*c)[4], float *ksum, const float *ksv, u64 *dnm) {
#pragma unroll 4
    for (int r = 0; r < 128; r++) {
        float4 a0 = A4[r * 32 + ty], a1 = A4[r * 32 + 16 + ty];
        float4 b0 = B4[r * 32 + tx], b1 = B4[r * 32 + 16 + tx];
        u64 bp0 = pk2(b0.x, b0.y), bp1 = pk2(b0.z, b0.w);
        u64 bp2 = pk2(b1.x, b1.y), bp3 = pk2(b1.z, b1.w);
        float av[8] = {a0.x, a0.y, a0.z, a0.w, a1.x, a1.y, a1.z, a1.w};
#pragma unroll
        for (int i = 0; i < 8; i++) {
            u64 ad = pk2(av[i], av[i]);
            fma2(c[i][0], ad, bp0); fma2(c[i][1], ad, bp1);
            fma2(c[i][2], ad, bp2); fma2(c[i][3], ad, bp3);
            if (KSUM) ksum[i] += av[i];
        }
        if (DEN) {
            u64 kd = pk2(ksv[r], ksv[r]);
            fma2(dnm[0], kd, bp0); fma2(dnm[1], kd, bp1);
            fma2(dnm[2], kd, bp2); fma2(dnm[3], kd, bp3);
        }
    }
}

// ---------------- Kernel T: V[b][v][l] -> VT[b][l][v] ----------------
__global__ __launch_bounds__(256, 1) void k_trans(const float *__restrict__ V) {
    extern __shared__ float ts[]; // 16384 floats, XOR-swizzled: word(v,l)=v*128+(l^(v>>2))
    int b = blockIdx.y, l0 = blockIdx.x * 128, t = threadIdx.x;
    int c4 = t & 31, r0 = t >> 5;
#pragma unroll
    for (int i = 0; i < 16; i++) {
        int v = i * 8 + r0, lb = c4 * 4;
        float4 g = *(const float4 *)(V + ((size_t)(b * 128 + v)) * Ll + l0 + lb);
        int s = v >> 2;
        ts[v * 128 + ((lb + 0) ^ s)] = g.x;
        ts[v * 128 + ((lb + 1) ^ s)] = g.y;
        ts[v * 128 + ((lb + 2) ^ s)] = g.z;
        ts[v * 128 + ((lb + 3) ^ s)] = g.w;
    }
    __syncthreads();
#pragma unroll
    for (int i = 0; i < 16; i++) {
        int l = i * 8 + r0, vb = (t & 31) * 4;
        float4 o; // (vb+k)>>2 == c4 for k<4 -> same xor as writes; reads conflict-free
        o.x = ts[(vb + 0) * 128 + (l ^ c4)];
        o.y = ts[(vb + 1) * 128 + (l ^ c4)];
        o.z = ts[(vb + 2) * 128 + (l ^ c4)];
        o.w = ts[(vb + 3) * 128 + (l ^ c4)];
        *(float4 *)(g_VT + ((size_t)b * Ll + l0 + l) * 128 + vb) = o;
    }
}

// ---------------- Kernel P1: phi_k + kv/ksum partials ----------------
__global__ __launch_bounds__(256, 1) void k_p1(const float *__restrict__ keys,
                                               const float *__restrict__ feats) {
    extern __shared__ float smem[];
    uint32_t sb = (uint32_t)__cvta_generic_to_shared(smem);
    const float4 *W4 = (const float4 *)smem;
    const float4 *Bf4 = (const float4 *)(smem + 16384);
    const float4 *Ph4 = (const float4 *)(smem + 32768);
    float4 *PhW = (float4 *)(smem + 32768);
    int b = blockIdx.y, ch = blockIdx.x, t = threadIdx.x;
    int ty = t >> 4, tx = t & 15;

    load_tile(sb, feats, 128); // W[d][m], natural layout
    cpcommit();

    u64 c2[8][4]; float ksm[8];
#pragma unroll
    for (int i = 0; i < 8; i++) {
        ksm[i] = 0.f;
#pragma unroll
        for (int j = 0; j < 4; j++) c2[i][j] = 0ull;
    }

    for (int st = 0; st < NSUB; st++) {
        int l0 = ch * (Ll / CH) + st * 128;
        __syncthreads(); // previous GEMM2 done with buf
        load_tile(sb + 65536, keys + (size_t)b * 128 * Ll + l0, Ll); // K[d][l]
        cpcommit(); cpwait(); __syncthreads();

        u64 p[8][4];
#pragma unroll
        for (int i = 0; i < 8; i++)
#pragma unroll
            for (int j = 0; j < 4; j++) p[i][j] = 0ull;

        // GEMM1: phi[l][m] = relu(K^T W)*s : A = K tile (ty = l), B = W (tx = m)
        mm128<false, false>(Bf4, W4, ty, tx, p, nullptr, nullptr, nullptr);

#pragma unroll
        for (int i = 0; i < 8; i++) {
            float v[8];
#pragma unroll
            for (int j = 0; j < 4; j++) {
                float2 f = upk2(p[i][j]);
                v[2 * j] = fmaxf(f.x * SCALE, 0.f);
                v[2 * j + 1] = fmaxf(f.y * SCALE, 0.f);
            }
            int row = ty * 8 + i; // l-local
            PhW[row * 32 + tx] = make_float4(v[0], v[1], v[2], v[3]);
            PhW[row * 32 + 16 + tx] = make_float4(v[4], v[5], v[6], v[7]);
        }
        __syncthreads(); // phi written; K reads done -> buf reusable
        load_tile(sb + 65536, g_VT + ((size_t)b * Ll + l0) * 128, 128); // VT[l][v]
        cpcommit(); cpwait(); __syncthreads();

        // GEMM2: kv[m][v] += phi^T ... A = phi[l][m-frag] (ty=m), B = VT[l][v-frag] (tx=v)
        mm128<true, false>(Ph4, Bf4, ty, tx, c2, ksm, nullptr, nullptr);
    }

    float *kvp = g_kvpart + (size_t)(b * CH + ch) * 16384;
#pragma unroll
    for (int i = 0; i < 8; i++) {
        float2 f0 = upk2(c2[i][0]), f1 = upk2(c2[i][1]);
        float2 f2 = upk2(c2[i][2]), f3 = upk2(c2[i][3]);
        float4 *dst = (float4 *)(kvp + (ty * 8 + i) * 128 + tx * 8);
        dst[0] = make_float4(f0.x, f0.y, f1.x, f1.y);
        dst[1] = make_float4(f2.x, f2.y, f3.x, f3.y);
    }
    if (tx == 0) {
#pragma unroll
        for (int i = 0; i < 8; i++)
            g_kspart[(b * CH + ch) * 128 + ty * 8 + i] = ksm[i];
    }
}

// ---------------- Kernel R: reduce partials ----------------
__global__ __launch_bounds__(256) void k_red() {
    int b = blockIdx.x >> 4, sl = blockIdx.x & 15, t = threadIdx.x;
    int e = sl * 1024 + t * 4;
    float4 acc = make_float4(0.f, 0.f, 0.f, 0.f);
#pragma unroll
    for (int ch = 0; ch < CH; ch++) {
        float4 v = *(const float4 *)(g_kvpart + (size_t)(b * CH + ch) * 16384 + e);
        acc.x += v.x; acc.y += v.y; acc.z += v.z; acc.w += v.w;
    }
    *(float4 *)(g_kv + (size_t)b * 16384 + e) = acc;
    if (sl == 0 && t < 128) {
        float s = 0.f;
#pragma unroll
        for (int ch = 0; ch < CH; ch++) s += g_kspart[(b * CH + ch) * 128 + t];
        g_ksum[b * 128 + t] = s;
    }
}

// ---------------- Kernel P2: phi_q + out ----------------
__global__ __launch_bounds__(256, 1) void k_p2(const float *__restrict__ queries,
                                               const float *__restrict__ feats,
                                               float *__restrict__ out) {
    extern __shared__ float smem[];
    uint32_t sb = (uint32_t)__cvta_generic_to_shared(smem);
    const float4 *W4 = (const float4 *)smem;
    const float4 *Bf4 = (const float4 *)(smem + 16384);
    const float4 *Ph4 = (const float4 *)(smem + 32768);
    float4 *PhW = (float4 *)(smem + 32768);
    const float *Ks = smem + 49152;
    int b = blockIdx.y, l0 = blockIdx.x * 128, t = threadIdx.x;
    int ty = t >> 4, tx = t & 15;

    load_tile(sb, feats, 128);
    load_tile(sb + 65536, queries + (size_t)b * 128 * Ll + l0, Ll);
    cpcommit(); cpwait(); __syncthreads();

    u64 p[8][4];
#pragma unroll
    for (int i = 0; i < 8; i++)
#pragma unroll
        for (int j = 0; j < 4; j++) p[i][j] = 0ull;

    // GEMM1: phi_q[m][l] : A = W (ty = m), B = Q tile (tx = l)
    mm128<false, false>(W4, Bf4, ty, tx, p, nullptr, nullptr, nullptr);

#pragma unroll
    for (int i = 0; i < 8; i++) {
        float v[8];
#pragma unroll
        for (int j = 0; j < 4; j++) {
            float2 f = upk2(p[i][j]);
            v[2 * j] = fmaxf(f.x * SCALE, 0.f);
            v[2 * j + 1] = fmaxf(f.y * SCALE, 0.f);
        }
        int row = ty * 8 + i; // m
        PhW[row * 32 + tx] = make_float4(v[0], v[1], v[2], v[3]);
        PhW[row * 32 + 16 + tx] = make_float4(v[4], v[5], v[6], v[7]);
    }
    __syncthreads();
    load_tile(sb + 65536, g_kv + (size_t)b * 16384, 128); // kv[m][v]
    if (t < 32) cp16(sb + 196608 + (uint32_t)t * 16, g_ksum + b * 128 + t * 4);
    cpcommit(); cpwait(); __syncthreads();

    u64 c2[8][4], dnm[4];
#pragma unroll
    for (int j = 0; j < 4; j++) dnm[j] = 0ull;
#pragma unroll
    for (int i = 0; i < 8; i++)
#pragma unroll
        for (int j = 0; j < 4; j++) c2[i][j] = 0ull;

    // GEMM2: out[v][l] = sum_m kv[m][v]*phi_q[m][l]; denom folded via ksum
    mm128<false, true>(Bf4, Ph4, ty, tx, c2, nullptr, Ks, dnm);

    float rl[8];
#pragma unroll
    for (int j = 0; j < 4; j++) {
        float2 d = upk2(dnm[j]);
        rl[2 * j] = rcp_nr(d.x);
        rl[2 * j + 1] = rcp_nr(d.y);
    }
#pragma unroll
    for (int i = 0; i < 8; i++) {
        float2 f0 = upk2(c2[i][0]), f1 = upk2(c2[i][1]);
        float2 f2 = upk2(c2[i][2]), f3 = upk2(c2[i][3]);
        float4 *dst = (float4 *)(out + ((size_t)(b * 128 + ty * 8 + i)) * Ll + l0 + tx * 8);
        dst[0] = make_float4(f0.x * rl[0], f0.y * rl[1], f1.x * rl[2], f1.y * rl[3]);
        dst[1] = make_float4(f2.x * rl[4], f2.y * rl[5], f3.x * rl[6], f3.y * rl[7]);
    }
}

// ---------------- launch ----------------
extern "C" void kernel_launch(void *const *d_in, const int *in_sizes, int n_in,
                              void *d_out, int out_size) {
    (void)in_sizes; (void)n_in; (void)out_size;
    const float *keys = (const float *)d_in[0];
    const float *values = (const float *)d_in[1];
    const float *queries = (const float *)d_in[2];
    const float *feats = (const float *)d_in[3];
    float *out = (float *)d_out;

    cudaFuncSetAttribute(k_trans, cudaFuncAttributeMaxDynamicSharedMemorySize, 65536);
    cudaFuncSetAttribute(k_p1, cudaFuncAttributeMaxDynamicSharedMemorySize, 197120);
    cudaFuncSetAttribute(k_p2, cudaFuncAttributeMaxDynamicSharedMemorySize, 197120);

    dim3 gt(Ll / 128, Bb);
    k_trans<<<gt, 256, 65536>>>(values);
    dim3 g1(CH, Bb);
    k_p1<<<g1, 256, 197120>>>(keys, feats);
    k_red<<<256, 256>>>();
    dim3 g2(Ll / 128, Bb);
    k_p2<<<g2, 256, 197120>>>(queries, feats, out);
}

// round 10
// speedup vs baseline: 1.6664x; 1.6622x over previous
#include <cuda_runtime.h>
#include <cstdint>
#include <cstddef>

#define DEV static __device__ __forceinline__

constexpr int Bb = 16, Ll = 8192;
constexpr int CH = 8;      // P1 l-chunks per batch
constexpr int NSUB = 8;    // 8 tiles of 128 per chunk
constexpr float SCALE = 0.08838834764831845f; // 1/sqrt(128)
constexpr int TS = 136;                        // smem tile row stride (floats)
constexpr int TILE_B = 128 * TS * 4;           // 69632 bytes per tile

// ---------------- scratch (device globals; no allocation) ----------------
__device__ __align__(16) float g_VT[(size_t)Bb * Ll * 128]; // V^T: [b][l][v] (tf32-rounded)
__device__ __align__(16) float g_kvpart[Bb * CH * 128 * 128];
__device__ __align__(16) float g_kspart[Bb * CH * 128];
__device__ __align__(16) float g_kv[Bb * 128 * 128];        // kv: [b][m][v] (tf32-rounded)
__device__ __align__(16) float g_ksum[Bb * 128];

// ---------------- helpers ----------------
DEV float rna(float x) { uint32_t r; asm("cvt.rna.tf32.f32 %0,%1;" : "=r"(r) : "f"(x)); return __uint_as_float(r); }
DEV float rcp_nr(float x) { float r; asm("rcp.approx.f32 %0,%1;" : "=f"(r) : "f"(x)); return r * (2.0f - x * r); }
DEV void cp16(uint32_t s, const void *g) { asm volatile("cp.async.ca.shared.global [%0],[%1],16;" :: "r"(s), "l"(g)); }
DEV void cpcommit() { asm volatile("cp.async.commit_group;"); }
template <int N> DEV void cpwait() { asm volatile("cp.async.wait_group %0;" :: "n"(N)); }

// m16n8k8 tf32 mma (legacy path, legal on compute_103; runs on tensor pipe)
DEV void mma8(float *d, const uint32_t *a, const uint32_t *b) {
    asm volatile("mma.sync.aligned.m16n8k8.row.col.f32.tf32.tf32.f32 "
                 "{%0,%1,%2,%3}, {%4,%5,%6,%7}, {%8,%9}, {%0,%1,%2,%3};"
                 : "+f"(d[0]), "+f"(d[1]), "+f"(d[2]), "+f"(d[3])
                 : "r"(a[0]), "r"(a[1]), "r"(a[2]), "r"(a[3]), "r"(b[0]), "r"(b[1]));
}

// Load 128x128 fp32 tile (global row stride gs floats) -> smem rows of stride TS.
DEV void load_tile(uint32_t sb, const float *g, size_t gs) {
    int t = threadIdx.x, c4 = t & 31, r0 = t >> 5;
#pragma unroll
    for (int i = 0; i < 16; i++) {
        int row = i * 8 + r0;
        cp16(sb + (uint32_t)(row * (TS * 4)) + (uint32_t)c4 * 16, g + (size_t)row * gs + c4 * 4);
    }
}

// In-place tf32 (rna) rounding of a 128x128 tile (stride TS).
DEV void rna_tile(float *s) {
    int t = threadIdx.x;
#pragma unroll
    for (int i = 0; i < 16; i++) {
        int idx = t + i * 256;              // 4096 float4 units
        int row = idx >> 5, c = (idx & 31) * 4;
        float4 *p = (float4 *)(s + row * TS + c);
        float4 v = *p;
        v.x = rna(v.x); v.y = rna(v.y); v.z = rna(v.z); v.w = rna(v.w);
        *p = v;
    }
}

// 128x128x128 warp-MMA GEMM: acc(+)= A^T*B with A,B k-major [k][*] in smem.
// 8 warps: warp (wid>>2) owns 64 M-rows, (wid&3) owns 32 N-cols.
DEV void wgemm(const float *As, const float *Bs, float (*acc)[4]) {
    int t = threadIdx.x, wid = t >> 5, lane = t & 31;
    int m0 = (wid >> 2) * 64, n0 = (wid & 3) * 32;
    int r = lane >> 2, c = lane & 3;
#pragma unroll
    for (int s = 0; s < 16; s++) {
        const float *ak = As + (s * 8 + c) * TS + r;
        const float *bk = Bs + (s * 8 + c) * TS + r;
        uint32_t a[4][4], b[4][2];
#pragma unroll
        for (int mt = 0; mt < 4; mt++) {
            int mo = m0 + mt * 16;
            a[mt][0] = __float_as_uint(ak[mo]);
            a[mt][1] = __float_as_uint(ak[mo + 8]);
            a[mt][2] = __float_as_uint(ak[4 * TS + mo]);
            a[mt][3] = __float_as_uint(ak[4 * TS + mo + 8]);
        }
#pragma unroll
        for (int nt = 0; nt < 4; nt++) {
            int no = n0 + nt * 8;
            b[nt][0] = __float_as_uint(bk[no]);
            b[nt][1] = __float_as_uint(bk[4 * TS + no]);
        }
#pragma unroll
        for (int mt = 0; mt < 4; mt++)
#pragma unroll
            for (int nt = 0; nt < 4; nt++)
                mma8(acc[mt * 4 + nt], a[mt], b[nt]);
    }
}

DEV void zero_acc(float (*a)[4]) {
#pragma unroll
    for (int i = 0; i < 16; i++)
#pragma unroll
        for (int j = 0; j < 4; j++) a[i][j] = 0.f;
}

// ---------------- Kernel T: V[b][v][l] -> VT[b][l][v] (+rna) ----------------
__global__ __launch_bounds__(256, 1) void k_trans(const float *__restrict__ V) {
    extern __shared__ float ts[]; // 16384 floats, XOR-swizzled
    int b = blockIdx.y, l0 = blockIdx.x * 128, t = threadIdx.x;
    int c4 = t & 31, r0 = t >> 5;
#pragma unroll
    for (int i = 0; i < 16; i++) {
        int v = i * 8 + r0, lb = c4 * 4;
        float4 g = *(const float4 *)(V + ((size_t)(b * 128 + v)) * Ll + l0 + lb);
        int s = v >> 2;
        ts[v * 128 + ((lb + 0) ^ s)] = rna(g.x);
        ts[v * 128 + ((lb + 1) ^ s)] = rna(g.y);
        ts[v * 128 + ((lb + 2) ^ s)] = rna(g.z);
        ts[v * 128 + ((lb + 3) ^ s)] = rna(g.w);
    }
    __syncthreads();
#pragma unroll
    for (int i = 0; i < 16; i++) {
        int l = i * 8 + r0, vb = c4 * 4;
        float4 o;
        o.x = ts[(vb + 0) * 128 + (l ^ c4)];
        o.y = ts[(vb + 1) * 128 + (l ^ c4)];
        o.z = ts[(vb + 2) * 128 + (l ^ c4)];
        o.w = ts[(vb + 3) * 128 + (l ^ c4)];
        *(float4 *)(g_VT + ((size_t)b * Ll + l0 + l) * 128 + vb) = o;
    }
}

// ---------------- P1: phi_k -> kv / ksum partials ----------------
// smem: W | bufA (K -> phi) | bufB (VT) | ksp[2][128]
__global__ __launch_bounds__(256, 1) void k_p1(const float *__restrict__ keys,
                                               const float *__restrict__ feats) {
    extern __shared__ float sm[];
    float *W = sm, *bufA = sm + 128 * TS, *bufB = sm + 2 * 128 * TS, *ksp = sm + 3 * 128 * TS;
    uint32_t sb = (uint32_t)__cvta_generic_to_shared(sm);
    uint32_t sbA = sb + TILE_B, sbB = sb + 2u * TILE_B;
    int b = blockIdx.y, ch = blockIdx.x, t = threadIdx.x;
    const float *Kbase = keys + (size_t)b * 128 * Ll + ch * 1024;
    const float *Vbase = g_VT + ((size_t)b * Ll + ch * 1024) * 128;

    load_tile(sb, feats, 128); cpcommit();            // W
    load_tile(sbA, Kbase, Ll); cpcommit();            // K0
    load_tile(sbB, Vbase, 128); cpcommit();           // V0 (prefetch)
    ksp[t] = 0.f;

    int wid = t >> 5, lane = t & 31;
    int m0 = (wid >> 2) * 64, n0 = (wid & 3) * 32;
    int r = lane >> 2, c = lane & 3;

    float kv[16][4];
    zero_acc(kv);

    for (int st = 0; st < NSUB; st++) {
        cpwait<1>(); __syncthreads();     // W..K[st] ready; V[st] may be in flight
        rna_tile(bufA);
        __syncthreads();

        float pa[16][4];
        zero_acc(pa);
        wgemm(bufA, W, pa);               // D[l][m] = K^T W
        __syncthreads();                  // all warps done with K tile

        // phi = rna(relu(D*scale)) -> bufA as [l][m]
#pragma unroll
        for (int mt = 0; mt < 4; mt++)
#pragma unroll
            for (int nt = 0; nt < 4; nt++) {
                float *d = pa[mt * 4 + nt];
                int Mr = m0 + mt * 16 + r, Nc = n0 + nt * 8 + 2 * c;
                float2 lo = {rna(fmaxf(d[0] * SCALE, 0.f)), rna(fmaxf(d[1] * SCALE, 0.f))};
                float2 hi = {rna(fmaxf(d[2] * SCALE, 0.f)), rna(fmaxf(d[3] * SCALE, 0.f))};
                *(float2 *)(bufA + Mr * TS + Nc) = lo;
                *(float2 *)(bufA + (Mr + 8) * TS + Nc) = hi;
            }
        __syncthreads();

        // ksum partial (column sums of phi)
        {
            int m = t & 127, lh = t >> 7;
            float s = 0.f;
#pragma unroll 8
            for (int j = 0; j < 64; j++) s += bufA[(lh * 64 + j) * TS + m];
            ksp[lh * 128 + m] += s;
        }

        cpwait<0>(); __syncthreads();     // V[st] ready
        wgemm(bufA, bufB, kv);            // kv[m][v] += phi^T VT
        __syncthreads();

        if (st + 1 < NSUB) {
            load_tile(sbA, Kbase + (st + 1) * 128, Ll); cpcommit();
            load_tile(sbB, Vbase + (size_t)(st + 1) * 128 * 128, 128); cpcommit();
        }
    }

    float *kvp = g_kvpart + (size_t)(b * CH + ch) * 16384;
#pragma unroll
    for (int mt = 0; mt < 4; mt++)
#pragma unroll
        for (int nt = 0; nt < 4; nt++) {
            float *d = kv[mt * 4 + nt];
            int Mr = m0 + mt * 16 + r, Nc = n0 + nt * 8 + 2 * c;
            *(float2 *)(kvp + Mr * 128 + Nc) = make_float2(d[0], d[1]);
            *(float2 *)(kvp + (Mr + 8) * 128 + Nc) = make_float2(d[2], d[3]);
        }
    __syncthreads();
    if (t < 128) g_kspart[(b * CH + ch) * 128 + t] = ksp[t] + ksp[128 + t];
}

// ---------------- reduce: partials -> kv (rna) + ksum ----------------
__global__ __launch_bounds__(128) void k_red() {
    int b = blockIdx.x, t = threadIdx.x;
#pragma unroll 4
    for (int m = 0; m < 128; m++) {
        float a = 0.f;
#pragma unroll
        for (int ch = 0; ch < CH; ch++)
            a += g_kvpart[((size_t)(b * CH + ch) * 128 + m) * 128 + t];
        g_kv[(size_t)b * 16384 + m * 128 + t] = rna(a);
    }
    float s = 0.f;
#pragma unroll
    for (int ch = 0; ch < CH; ch++) s += g_kspart[(b * CH + ch) * 128 + t];
    g_ksum[b * 128 + t] = s;
}

// ---------------- P2: phi_q -> out ----------------
// smem: W | bufQ (Q -> kv) | phi (phi -> out-stage) | ks[128] | denp[2][128] | rden[128]
__global__ __launch_bounds__(256, 1) void k_p2(const float *__restrict__ queries,
                                               const float *__restrict__ feats,
                                               float *__restrict__ out) {
    extern __shared__ float sm[];
    float *W = sm, *bufQ = sm + 128 * TS, *phi = sm + 2 * 128 * TS;
    float *ks = sm + 3 * 128 * TS, *denp = ks + 128, *rden = denp + 256;
    uint32_t sb = (uint32_t)__cvta_generic_to_shared(sm);
    uint32_t sbQ = sb + TILE_B;
    uint32_t sbKS = sb + 3u * TILE_B;
    int b = blockIdx.y, l0 = blockIdx.x * 128, t = threadIdx.x;

    load_tile(sb, feats, 128);
    load_tile(sbQ, queries + (size_t)b * 128 * Ll + l0, Ll);
    if (t < 32) cp16(sbKS + (uint32_t)t * 16, g_ksum + b * 128 + t * 4);
    cpcommit();
    cpwait<0>(); __syncthreads();
    rna_tile(W);
    rna_tile(bufQ);
    __syncthreads();

    int wid = t >> 5, lane = t & 31;
    int m0 = (wid >> 2) * 64, n0 = (wid & 3) * 32;
    int r = lane >> 2, c = lane & 3;

    float pa[16][4];
    zero_acc(pa);
    wgemm(W, bufQ, pa);            // D[m][l] = W^T Q
    __syncthreads();               // done with Q tile

    load_tile(sbQ, g_kv + (size_t)b * 16384, 128); cpcommit();  // prefetch kv

    // phi = rna(relu(D*scale)) -> phi buffer as [m][l]
#pragma unroll
    for (int mt = 0; mt < 4; mt++)
#pragma unroll
        for (int nt = 0; nt < 4; nt++) {
            float *d = pa[mt * 4 + nt];
            int Mr = m0 + mt * 16 + r, Nc = n0 + nt * 8 + 2 * c;
            float2 lo = {rna(fmaxf(d[0] * SCALE, 0.f)), rna(fmaxf(d[1] * SCALE, 0.f))};
            float2 hi = {rna(fmaxf(d[2] * SCALE, 0.f)), rna(fmaxf(d[3] * SCALE, 0.f))};
            *(float2 *)(phi + Mr * TS + Nc) = lo;
            *(float2 *)(phi + (Mr + 8) * TS + Nc) = hi;
        }
    __syncthreads();

    // denominator: den[l] = sum_m phi[m][l] * ksum[m]
    {
        int l = t & 127, mh = t >> 7;
        float s = 0.f;
#pragma unroll 8
        for (int j = 0; j < 64; j++) {
            int m = mh * 64 + j;
            s = fmaf(phi[m * TS + l], ks[m], s);
        }
        denp[mh * 128 + l] = s;
    }
    __syncthreads();
    if (t < 128) rden[t] = rcp_nr(denp[t] + denp[128 + t]);
    cpwait<0>(); __syncthreads();   // kv ready (pre-rounded in k_red)

    float oa[16][4];
    zero_acc(oa);
    wgemm(bufQ, phi, oa);           // D[v][l] = kv^T phi_q
    __syncthreads();                // phi free -> reuse as out stage

#pragma unroll
    for (int mt = 0; mt < 4; mt++)
#pragma unroll
        for (int nt = 0; nt < 4; nt++) {
            float *d = oa[mt * 4 + nt];
            int Mr = m0 + mt * 16 + r, Nc = n0 + nt * 8 + 2 * c;
            *(float2 *)(phi + Mr * TS + Nc) = make_float2(d[0], d[1]);
            *(float2 *)(phi + (Mr + 8) * TS + Nc) = make_float2(d[2], d[3]);
        }
    __syncthreads();

    // coalesced store: out[v][l] = stage * rden[l]
#pragma unroll
    for (int i = 0; i < 16; i++) {
        int v = i * 8 + (t >> 5), l = (t & 31) * 4;
        float4 x = *(float4 *)(phi + v * TS + l);
        float4 dd = *(float4 *)(rden + l);
        x.x *= dd.x; x.y *= dd.y; x.z *= dd.z; x.w *= dd.w;
        *(float4 *)(out + (size_t)(b * 128 + v) * Ll + l0 + l) = x;
    }
}

// ---------------- launch ----------------
extern "C" void kernel_launch(void *const *d_in, const int *in_sizes, int n_in,
                              void *d_out, int out_size) {
    (void)in_sizes; (void)n_in; (void)out_size;
    const float *keys = (const float *)d_in[0];
    const float *values = (const float *)d_in[1];
    const float *queries = (const float *)d_in[2];
    const float *feats = (const float *)d_in[3];
    float *out = (float *)d_out;

    constexpr int SM_P1 = 3 * TILE_B + 256 * 4;          // 209920
    constexpr int SM_P2 = 3 * TILE_B + (128 + 256 + 128) * 4; // 210944

    cudaFuncSetAttribute(k_trans, cudaFuncAttributeMaxDynamicSharedMemorySize, 65536);
    cudaFuncSetAttribute(k_p1, cudaFuncAttributeMaxDynamicSharedMemorySize, SM_P1);
    cudaFuncSetAttribute(k_p2, cudaFuncAttributeMaxDynamicSharedMemorySize, SM_P2);

    k_trans<<<dim3(Ll / 128, Bb), 256, 65536>>>(values);
    k_p1<<<dim3(CH, Bb), 256, SM_P1>>>(keys, feats);
    k_red<<<Bb, 128>>>();
    k_p2<<<dim3(Ll / 128, Bb), 256, SM_P2>>>(queries, feats, out);
}

// round 11
// speedup vs baseline: 2.2577x; 1.3548x over previous
#include <cuda_runtime.h>
#include <cstdint>
#include <cstddef>

#define DEV static __device__ __forceinline__

constexpr int Bb = 16, Ll = 8192;
constexpr int CH = 8;      // P1 l-chunks per batch
constexpr int NSUB = 8;    // 8 tiles of 128 per chunk
constexpr float SCALE = 0.08838834764831845f; // 1/sqrt(128)
constexpr int TS = 136;    // k-major smem tile row stride (floats)
constexpr int TSV = 132;   // n-major (V) smem tile row stride (floats)
constexpr int TILE_B = 128 * TS * 4;   // 69632 bytes
constexpr int TILEV_B = 128 * TSV * 4; // 67584 bytes

// ---------------- scratch (device globals; no allocation) ----------------
__device__ __align__(16) float g_kvpart[Bb * CH * 128 * 128];
__device__ __align__(16) float g_kspart[Bb * CH * 128];
__device__ __align__(16) float g_kv[Bb * 128 * 128];  // kv: [b][m][v] (tf32-rounded)
__device__ __align__(16) float g_ksum[Bb * 128];

// ---------------- helpers ----------------
DEV float rna(float x) { uint32_t r; asm("cvt.rna.tf32.f32 %0,%1;" : "=r"(r) : "f"(x)); return __uint_as_float(r); }
DEV float rcp_nr(float x) { float r; asm("rcp.approx.f32 %0,%1;" : "=f"(r) : "f"(x)); return r * (2.0f - x * r); }
DEV void cp16(uint32_t s, const void *g) { asm volatile("cp.async.ca.shared.global [%0],[%1],16;" :: "r"(s), "l"(g)); }
DEV void cpcommit() { asm volatile("cp.async.commit_group;"); }
template <int N> DEV void cpwait() { asm volatile("cp.async.wait_group %0;" :: "n"(N)); }

// m16n8k8 tf32 mma (legal on compute_103; runs on the tensor pipe)
DEV void mma8(float *d, const uint32_t *a, const uint32_t *b) {
    asm volatile("mma.sync.aligned.m16n8k8.row.col.f32.tf32.tf32.f32 "
                 "{%0,%1,%2,%3}, {%4,%5,%6,%7}, {%8,%9}, {%0,%1,%2,%3};"
                 : "+f"(d[0]), "+f"(d[1]), "+f"(d[2]), "+f"(d[3])
                 : "r"(a[0]), "r"(a[1]), "r"(a[2]), "r"(a[3]), "r"(b[0]), "r"(b[1]));
}

// Load 128x128 fp32 tile (global row stride gs floats) -> smem rows of stride ss.
// 512 threads, 8 x cp16 each.
DEV void load_tile(uint32_t sb, const float *g, size_t gs, int ss) {
    int t = threadIdx.x, c4 = t & 31, r0 = t >> 5;
#pragma unroll
    for (int i = 0; i < 8; i++) {
        int row = i * 16 + r0;
        cp16(sb + (uint32_t)(row * ss * 4) + (uint32_t)c4 * 16, g + (size_t)row * gs + c4 * 4);
    }
}

// In-place tf32 (rna) rounding of a 128x128 tile (stride ss). 512 threads.
DEV void rna_tile(float *s, int ss) {
    int t = threadIdx.x;
#pragma unroll
    for (int i = 0; i < 8; i++) {
        int idx = t + i * 512;   // 4096 float4 units
        int row = idx >> 5, c = (idx & 31) * 4;
        float4 *p = (float4 *)(s + row * ss + c);
        float4 v = *p;
        v.x = rna(v.x); v.y = rna(v.y); v.z = rna(v.z); v.w = rna(v.w);
        *p = v;
    }
}

// ---------------- 128x128x128 warp-MMA GEMM, 16 warps, warp tile 32x32 ------
// acc(+)= A^T*B ; A k-major [k][m] stride TS, B k-major [k][n] stride TS.
DEV void wgemm(const float *As, const float *Bs, float (*acc)[4]) {
    int t = threadIdx.x, wid = t >> 5, lane = t & 31;
    int m0 = (wid >> 2) * 32, n0 = (wid & 3) * 32;
    int r = lane >> 2, c = lane & 3;
#pragma unroll
    for (int s = 0; s < 16; s++) {
        const float *ak = As + (s * 8 + c) * TS + r;
        const float *bk = Bs + (s * 8 + c) * TS + r;
        uint32_t a[2][4], b[4][2];
#pragma unroll
        for (int mt = 0; mt < 2; mt++) {
            int mo = m0 + mt * 16;
            a[mt][0] = __float_as_uint(ak[mo]);
            a[mt][1] = __float_as_uint(ak[mo + 8]);
            a[mt][2] = __float_as_uint(ak[4 * TS + mo]);
            a[mt][3] = __float_as_uint(ak[4 * TS + mo + 8]);
        }
#pragma unroll
        for (int nt = 0; nt < 4; nt++) {
            int no = n0 + nt * 8;
            b[nt][0] = __float_as_uint(bk[no]);
            b[nt][1] = __float_as_uint(bk[4 * TS + no]);
        }
#pragma unroll
        for (int mt = 0; mt < 2; mt++)
#pragma unroll
            for (int nt = 0; nt < 4; nt++)
                mma8(acc[mt * 4 + nt], a[mt], b[nt]);
    }
}

// Same, but B is n-major [n][k] stride TSV (reads V in its NATIVE layout).
// Per-instruction bank index = 4*(lane>>2)+(lane&3) = lane -> conflict-free.
DEV void wgemm_bn(const float *As, const float *Bs, float (*acc)[4]) {
    int t = threadIdx.x, wid = t >> 5, lane = t & 31;
    int m0 = (wid >> 2) * 32, n0 = (wid & 3) * 32;
    int r = lane >> 2, c = lane & 3;
#pragma unroll
    for (int s = 0; s < 16; s++) {
        const float *ak = As + (s * 8 + c) * TS + r;
        uint32_t a[2][4], b[4][2];
#pragma unroll
        for (int mt = 0; mt < 2; mt++) {
            int mo = m0 + mt * 16;
            a[mt][0] = __float_as_uint(ak[mo]);
            a[mt][1] = __float_as_uint(ak[mo + 8]);
            a[mt][2] = __float_as_uint(ak[4 * TS + mo]);
            a[mt][3] = __float_as_uint(ak[4 * TS + mo + 8]);
        }
#pragma unroll
        for (int nt = 0; nt < 4; nt++) {
            const float *bn = Bs + (n0 + nt * 8 + r) * TSV + s * 8 + c;
            b[nt][0] = __float_as_uint(bn[0]);
            b[nt][1] = __float_as_uint(bn[4]);
        }
#pragma unroll
        for (int mt = 0; mt < 2; mt++)
#pragma unroll
            for (int nt = 0; nt < 4; nt++)
                mma8(acc[mt * 4 + nt], a[mt], b[nt]);
    }
}

DEV void zero_acc(float (*a)[4]) {
#pragma unroll
    for (int i = 0; i < 8; i++)
#pragma unroll
        for (int j = 0; j < 4; j++) a[i][j] = 0.f;
}

// ---------------- P1: phi_k -> kv / ksum partials ----------------
// smem: W(TS) | bufA(TS: K -> phi) | bufV(TSV: V native) | ksp[4][128]
__global__ __launch_bounds__(512, 1) void k_p1(const float *__restrict__ keys,
                                               const float *__restrict__ V,
                                               const float *__restrict__ feats) {
    extern __shared__ float sm[];
    float *W = sm, *bufA = sm + 128 * TS, *bufV = sm + 2 * 128 * TS;
    float *ksp = sm + 2 * 128 * TS + 128 * TSV;
    uint32_t sb = (uint32_t)__cvta_generic_to_shared(sm);
    uint32_t sbA = sb + TILE_B, sbV = sb + 2u * TILE_B;
    int b = blockIdx.y, ch = blockIdx.x, t = threadIdx.x;
    const float *Kbase = keys + (size_t)b * 128 * Ll + ch * 1024;
    const float *Vbase = V + (size_t)b * 128 * Ll + ch * 1024;

    load_tile(sb, feats, 128, TS); cpcommit();     // W
    load_tile(sbA, Kbase, Ll, TS); cpcommit();     // K0
    load_tile(sbV, Vbase, Ll, TSV); cpcommit();    // V0 (native [v][l])
    ksp[t] = 0.f;

    int wid = t >> 5, lane = t & 31;
    int m0 = (wid >> 2) * 32, n0 = (wid & 3) * 32;
    int r = lane >> 2, c = lane & 3;

    float kv[8][4];
    zero_acc(kv);

    for (int st = 0; st < NSUB; st++) {
        cpwait<1>(); __syncthreads();     // W + K[st] ready; V[st] may be in flight
        rna_tile(bufA, TS);
        if (st == 0) rna_tile(W, TS);
        __syncthreads();

        float pa[8][4];
        zero_acc(pa);
        wgemm(bufA, W, pa);               // D[l][m] = K^T W
        __syncthreads();                  // all warps done with K tile

        // phi = rna(relu(D*scale)) -> bufA as [l][m]
#pragma unroll
        for (int mt = 0; mt < 2; mt++)
#pragma unroll
            for (int nt = 0; nt < 4; nt++) {
                float *d = pa[mt * 4 + nt];
                int Mr = m0 + mt * 16 + r, Nc = n0 + nt * 8 + 2 * c;
                float2 lo = {rna(fmaxf(d[0] * SCALE, 0.f)), rna(fmaxf(d[1] * SCALE, 0.f))};
                float2 hi = {rna(fmaxf(d[2] * SCALE, 0.f)), rna(fmaxf(d[3] * SCALE, 0.f))};
                *(float2 *)(bufA + Mr * TS + Nc) = lo;
                *(float2 *)(bufA + (Mr + 8) * TS + Nc) = hi;
            }
        __syncthreads();

        // ksum partial (column sums of phi)
        {
            int m = t & 127, lh = t >> 7;
            float s = 0.f;
#pragma unroll 8
            for (int j = 0; j < 32; j++) s += bufA[(lh * 32 + j) * TS + m];
            ksp[lh * 128 + m] += s;
        }

        cpwait<0>(); __syncthreads();     // V[st] ready
        rna_tile(bufV, TSV);
        __syncthreads();
        wgemm_bn(bufA, bufV, kv);         // kv[m][v] += phi^T V^T (V native)
        __syncthreads();

        if (st + 1 < NSUB) {
            load_tile(sbA, Kbase + (st + 1) * 128, Ll, TS); cpcommit();
            load_tile(sbV, Vbase + (st + 1) * 128, Ll, TSV); cpcommit();
        }
    }

    float *kvp = g_kvpart + (size_t)(b * CH + ch) * 16384;
#pragma unroll
    for (int mt = 0; mt < 2; mt++)
#pragma unroll
        for (int nt = 0; nt < 4; nt++) {
            float *d = kv[mt * 4 + nt];
            int Mr = m0 + mt * 16 + r, Nc = n0 + nt * 8 + 2 * c;
            *(float2 *)(kvp + Mr * 128 + Nc) = make_float2(d[0], d[1]);
            *(float2 *)(kvp + (Mr + 8) * 128 + Nc) = make_float2(d[2], d[3]);
        }
    __syncthreads();
    if (t < 128) g_kspart[(b * CH + ch) * 128 + t] =
        ksp[t] + ksp[128 + t] + ksp[256 + t] + ksp[384 + t];
}

// ---------------- reduce: partials -> kv (rna) + ksum ----------------
__global__ __launch_bounds__(256) void k_red() {
    int mg = blockIdx.x, b = blockIdx.y, t = threadIdx.x;
    int v = (t & 31) * 4, mr = t >> 5;
#pragma unroll
    for (int i = 0; i < 2; i++) {
        int m = mg * 16 + i * 8 + mr;
        float4 a = make_float4(0.f, 0.f, 0.f, 0.f);
#pragma unroll
        for (int ch = 0; ch < CH; ch++) {
            float4 x = *(const float4 *)(g_kvpart + ((size_t)(b * CH + ch) * 128 + m) * 128 + v);
            a.x += x.x; a.y += x.y; a.z += x.z; a.w += x.w;
        }
        a.x = rna(a.x); a.y = rna(a.y); a.z = rna(a.z); a.w = rna(a.w);
        *(float4 *)(g_kv + (size_t)b * 16384 + m * 128 + v) = a;
    }
    if (mg == 0 && t < 128) {
        float s = 0.f;
#pragma unroll
        for (int ch = 0; ch < CH; ch++) s += g_kspart[(b * CH + ch) * 128 + t];
        g_ksum[b * 128 + t] = s;
    }
}

// ---------------- P2: phi_q -> out ----------------
// smem: W | bufQ (Q -> kv) | phi (phi -> out-stage) | ks[128] | denp[4][128] | rden[128]
__global__ __launch_bounds__(512, 1) void k_p2(const float *__restrict__ queries,
                                               const float *__restrict__ feats,
                                               float *__restrict__ out) {
    extern __shared__ float sm[];
    float *W = sm, *bufQ = sm + 128 * TS, *phi = sm + 2 * 128 * TS;
    float *ks = sm + 3 * 128 * TS, *denp = ks + 128, *rden = denp + 512;
    uint32_t sb = (uint32_t)__cvta_generic_to_shared(sm);
    uint32_t sbQ = sb + TILE_B;
    uint32_t sbKS = sb + 3u * TILE_B;
    int b = blockIdx.y, l0 = blockIdx.x * 128, t = threadIdx.x;

    load_tile(sb, feats, 128, TS);
    load_tile(sbQ, queries + (size_t)b * 128 * Ll + l0, Ll, TS);
    if (t < 32) cp16(sbKS + (uint32_t)t * 16, g_ksum + b * 128 + t * 4);
    cpcommit();
    cpwait<0>(); __syncthreads();
    rna_tile(W, TS);
    rna_tile(bufQ, TS);
    __syncthreads();

    int wid = t >> 5, lane = t & 31;
    int m0 = (wid >> 2) * 32, n0 = (wid & 3) * 32;
    int r = lane >> 2, c = lane & 3;

    float pa[8][4];
    zero_acc(pa);
    wgemm(W, bufQ, pa);            // D[m][l] = W^T Q
    __syncthreads();               // done with Q tile

    load_tile(sbQ, g_kv + (size_t)b * 16384, 128, TS); cpcommit();  // prefetch kv

    // phi = rna(relu(D*scale)) -> phi buffer as [m][l]
#pragma unroll
    for (int mt = 0; mt < 2; mt++)
#pragma unroll
        for (int nt = 0; nt < 4; nt++) {
            float *d = pa[mt * 4 + nt];
            int Mr = m0 + mt * 16 + r, Nc = n0 + nt * 8 + 2 * c;
            float2 lo = {rna(fmaxf(d[0] * SCALE, 0.f)), rna(fmaxf(d[1] * SCALE, 0.f))};
            float2 hi = {rna(fmaxf(d[2] * SCALE, 0.f)), rna(fmaxf(d[3] * SCALE, 0.f))};
            *(float2 *)(phi + Mr * TS + Nc) = lo;
            *(float2 *)(phi + (Mr + 8) * TS + Nc) = hi;
        }
    __syncthreads();

    // denominator: den[l] = sum_m phi[m][l] * ksum[m]
    {
        int l = t & 127, mh = t >> 7;
        float s = 0.f;
#pragma unroll 8
        for (int j = 0; j < 32; j++) {
            int m = mh * 32 + j;
            s = fmaf(phi[m * TS + l], ks[m], s);
        }
        denp[mh * 128 + l] = s;
    }
    __syncthreads();
    if (t < 128) rden[t] = rcp_nr(denp[t] + denp[128 + t] + denp[256 + t] + denp[384 + t]);
    cpwait<0>(); __syncthreads();   // kv ready (pre-rounded in k_red)

    float oa[8][4];
    zero_acc(oa);
    wgemm(bufQ, phi, oa);           // D[v][l] = kv^T phi_q
    __syncthreads();                // phi free -> reuse as out stage

#pragma unroll
    for (int mt = 0; mt < 2; mt++)
#pragma unroll
        for (int nt = 0; nt < 4; nt++) {
            float *d = oa[mt * 4 + nt];
            int Mr = m0 + mt * 16 + r, Nc = n0 + nt * 8 + 2 * c;
            *(float2 *)(phi + Mr * TS + Nc) = make_float2(d[0], d[1]);
            *(float2 *)(phi + (Mr + 8) * TS + Nc) = make_float2(d[2], d[3]);
        }
    __syncthreads();

    // coalesced store: out[v][l] = stage * rden[l]
#pragma unroll
    for (int i = 0; i < 8; i++) {
        int v = i * 16 + (t >> 5), l = (t & 31) * 4;
        float4 x = *(float4 *)(phi + v * TS + l);
        float4 dd = *(float4 *)(rden + l);
        x.x *= dd.x; x.y *= dd.y; x.z *= dd.z; x.w *= dd.w;
        *(float4 *)(out + (size_t)(b * 128 + v) * Ll + l0 + l) = x;
    }
}

// ---------------- launch ----------------
extern "C" void kernel_launch(void *const *d_in, const int *in_sizes, int n_in,
                              void *d_out, int out_size) {
    (void)in_sizes; (void)n_in; (void)out_size;
    const float *keys = (const float *)d_in[0];
    const float *values = (const float *)d_in[1];
    const float *queries = (const float *)d_in[2];
    const float *feats = (const float *)d_in[3];
    float *out = (float *)d_out;

    constexpr int SM_P1 = 2 * TILE_B + TILEV_B + 512 * 4;          // 208896
    constexpr int SM_P2 = 3 * TILE_B + (128 + 512 + 128) * 4;      // 211968

    cudaFuncSetAttribute(k_p1, cudaFuncAttributeMaxDynamicSharedMemorySize, SM_P1);
    cudaFuncSetAttribute(k_p2, cudaFuncAttributeMaxDynamicSharedMemorySize, SM_P2);

    k_p1<<<dim3(CH, Bb), 512, SM_P1>>>(keys, values, feats);
    k_red<<<dim3(8, Bb), 256>>>();
    k_p2<<<dim3(Ll / 128, Bb), 512, SM_P2>>>(queries, feats, out);
}

// round 12
// speedup vs baseline: 2.4567x; 1.0881x over previous
#include <cuda_runtime.h>
#include <cstdint>
#include <cstddef>

#define DEV static __device__ __forceinline__

constexpr int Bb = 16, Ll = 8192;
constexpr int CH = 8;      // P1 l-chunks per batch
constexpr int NSUB = 8;    // 8 tiles of 128 per chunk
constexpr int TPB2 = 4;    // P2 l-tiles per block
constexpr float SCALE = 0.08838834764831845f; // 1/sqrt(128)
constexpr int TS = 136;    // k-major smem tile row stride (floats)
constexpr int TSV = 132;   // n-major (V) smem tile row stride (floats)
constexpr int TILE_B = 128 * TS * 4;   // 69632 bytes
constexpr int TILEV_B = 128 * TSV * 4; // 67584 bytes

// ---------------- scratch (device globals; no allocation) ----------------
__device__ __align__(16) float g_kvpart[Bb * CH * 128 * 128];
__device__ __align__(16) float g_kspart[Bb * CH * 128];
__device__ __align__(16) float g_kv[Bb * 128 * 128];  // kv: [b][m][v] (tf32-rounded)
__device__ __align__(16) float g_ksum[Bb * 128];

// ---------------- helpers ----------------
DEV float rna(float x) { uint32_t r; asm("cvt.rna.tf32.f32 %0,%1;" : "=r"(r) : "f"(x)); return __uint_as_float(r); }
DEV float rcp_nr(float x) { float r; asm("rcp.approx.f32 %0,%1;" : "=f"(r) : "f"(x)); return r * (2.0f - x * r); }
DEV void cp16(uint32_t s, const void *g) { asm volatile("cp.async.ca.shared.global [%0],[%1],16;" :: "r"(s), "l"(g)); }
DEV void cpcommit() { asm volatile("cp.async.commit_group;"); }
template <int N> DEV void cpwait() { asm volatile("cp.async.wait_group %0;" :: "n"(N)); }

// m16n8k8 tf32 mma (legal on compute_103; runs on the tensor pipe)
DEV void mma8(float *d, const uint32_t *a, const uint32_t *b) {
    asm volatile("mma.sync.aligned.m16n8k8.row.col.f32.tf32.tf32.f32 "
                 "{%0,%1,%2,%3}, {%4,%5,%6,%7}, {%8,%9}, {%0,%1,%2,%3};"
                 : "+f"(d[0]), "+f"(d[1]), "+f"(d[2]), "+f"(d[3])
                 : "r"(a[0]), "r"(a[1]), "r"(a[2]), "r"(a[3]), "r"(b[0]), "r"(b[1]));
}

// Load 128x128 fp32 tile (global row stride gs floats) -> smem rows of stride ss.
// 512 threads, 8 x cp16 each.
DEV void load_tile(uint32_t sb, const float *g, size_t gs, int ss) {
    int t = threadIdx.x, c4 = t & 31, r0 = t >> 5;
#pragma unroll
    for (int i = 0; i < 8; i++) {
        int row = i * 16 + r0;
        cp16(sb + (uint32_t)(row * ss * 4) + (uint32_t)c4 * 16, g + (size_t)row * gs + c4 * 4);
    }
}

// In-place tf32 (rna) rounding of a 128x128 tile (stride ss). 512 threads.
DEV void rna_tile(float *s, int ss) {
    int t = threadIdx.x;
#pragma unroll
    for (int i = 0; i < 8; i++) {
        int idx = t + i * 512;   // 4096 float4 units
        int row = idx >> 5, c = (idx & 31) * 4;
        float4 *p = (float4 *)(s + row * ss + c);
        float4 v = *p;
        v.x = rna(v.x); v.y = rna(v.y); v.z = rna(v.z); v.w = rna(v.w);
        *p = v;
    }
}

// ---------------- 128x128x128 warp-MMA GEMM, 16 warps, warp tile 32x32 ------
// acc(+)= A^T*B ; A k-major [k][m] stride TS, B k-major [k][n] stride TS.
DEV void wgemm(const float *As, const float *Bs, float (*acc)[4]) {
    int t = threadIdx.x, wid = t >> 5, lane = t & 31;
    int m0 = (wid >> 2) * 32, n0 = (wid & 3) * 32;
    int r = lane >> 2, c = lane & 3;
#pragma unroll
    for (int s = 0; s < 16; s++) {
        const float *ak = As + (s * 8 + c) * TS + r;
        const float *bk = Bs + (s * 8 + c) * TS + r;
        uint32_t a[2][4], b[4][2];
#pragma unroll
        for (int mt = 0; mt < 2; mt++) {
            int mo = m0 + mt * 16;
            a[mt][0] = __float_as_uint(ak[mo]);
            a[mt][1] = __float_as_uint(ak[mo + 8]);
            a[mt][2] = __float_as_uint(ak[4 * TS + mo]);
            a[mt][3] = __float_as_uint(ak[4 * TS + mo + 8]);
        }
#pragma unroll
        for (int nt = 0; nt < 4; nt++) {
            int no = n0 + nt * 8;
            b[nt][0] = __float_as_uint(bk[no]);
            b[nt][1] = __float_as_uint(bk[4 * TS + no]);
        }
#pragma unroll
        for (int mt = 0; mt < 2; mt++)
#pragma unroll
            for (int nt = 0; nt < 4; nt++)
                mma8(acc[mt * 4 + nt], a[mt], b[nt]);
    }
}

// Same, but B is n-major [n][k] stride TSV (reads V in its NATIVE layout).
DEV void wgemm_bn(const float *As, const float *Bs, float (*acc)[4]) {
    int t = threadIdx.x, wid = t >> 5, lane = t & 31;
    int m0 = (wid >> 2) * 32, n0 = (wid & 3) * 32;
    int r = lane >> 2, c = lane & 3;
#pragma unroll
    for (int s = 0; s < 16; s++) {
        const float *ak = As + (s * 8 + c) * TS + r;
        uint32_t a[2][4], b[4][2];
#pragma unroll
        for (int mt = 0; mt < 2; mt++) {
            int mo = m0 + mt * 16;
            a[mt][0] = __float_as_uint(ak[mo]);
            a[mt][1] = __float_as_uint(ak[mo + 8]);
            a[mt][2] = __float_as_uint(ak[4 * TS + mo]);
            a[mt][3] = __float_as_uint(ak[4 * TS + mo + 8]);
        }
#pragma unroll
        for (int nt = 0; nt < 4; nt++) {
            const float *bn = Bs + (n0 + nt * 8 + r) * TSV + s * 8 + c;
            b[nt][0] = __float_as_uint(bn[0]);
            b[nt][1] = __float_as_uint(bn[4]);
        }
#pragma unroll
        for (int mt = 0; mt < 2; mt++)
#pragma unroll
            for (int nt = 0; nt < 4; nt++)
                mma8(acc[mt * 4 + nt], a[mt], b[nt]);
    }
}

DEV void zero_acc(float (*a)[4]) {
#pragma unroll
    for (int i = 0; i < 8; i++)
#pragma unroll
        for (int j = 0; j < 4; j++) a[i][j] = 0.f;
}

DEV float shfl_red(float s) {
    s += __shfl_xor_sync(0xffffffffu, s, 4);
    s += __shfl_xor_sync(0xffffffffu, s, 8);
    s += __shfl_xor_sync(0xffffffffu, s, 16);
    return s;
}

// ---------------- P1: phi_k -> kv / ksum partials ----------------
// smem: W(TS) | bufA(TS: K -> phi) | bufV(TSV: V native) | ksp[4][128]
__global__ __launch_bounds__(512, 1) void k_p1(const float *__restrict__ keys,
                                               const float *__restrict__ V,
                                               const float *__restrict__ feats) {
    extern __shared__ float sm[];
    float *W = sm, *bufA = sm + 128 * TS, *bufV = sm + 2 * 128 * TS;
    float *ksp = sm + 2 * 128 * TS + 128 * TSV;
    uint32_t sb = (uint32_t)__cvta_generic_to_shared(sm);
    uint32_t sbA = sb + TILE_B, sbV = sb + 2u * TILE_B;
    int b = blockIdx.y, ch = blockIdx.x, t = threadIdx.x;
    const float *Kbase = keys + (size_t)b * 128 * Ll + ch * 1024;
    const float *Vbase = V + (size_t)b * 128 * Ll + ch * 1024;

    load_tile(sb, feats, 128, TS);                 // W  (group A)
    load_tile(sbA, Kbase, Ll, TS); cpcommit();     // K0 (group A)
    load_tile(sbV, Vbase, Ll, TSV); cpcommit();    // V0 (group B)
    ksp[t] = 0.f;

    int wid = t >> 5, lane = t & 31;
    int m0 = (wid >> 2) * 32, n0 = (wid & 3) * 32;
    int r = lane >> 2, c = lane & 3;
    int wr = wid >> 2;

    float kv[8][4];
    zero_acc(kv);

    for (int st = 0; st < NSUB; st++) {
        cpwait<1>(); __syncthreads();     // W + K[st] ready (V may be in flight)

        float pa[8][4];
        zero_acc(pa);
        wgemm(bufA, W, pa);               // D[l][m] = K^T W  (HW truncates K,W)
        cpwait<0>();                      // V[st] arrived (this thread)
        __syncthreads();                  // gemm1 done + all cp visible

        // epilogue: phi = rna(relu(D*scale)) -> bufA[l][m]; ksum fold; rna V
#pragma unroll
        for (int nt = 0; nt < 4; nt++) {
            float s0 = 0.f, s1 = 0.f;
            int Nc = n0 + nt * 8 + 2 * c;
#pragma unroll
            for (int mt = 0; mt < 2; mt++) {
                float *d = pa[mt * 4 + nt];
                int Mr = m0 + mt * 16 + r;
                float2 lo = {rna(fmaxf(d[0] * SCALE, 0.f)), rna(fmaxf(d[1] * SCALE, 0.f))};
                float2 hi = {rna(fmaxf(d[2] * SCALE, 0.f)), rna(fmaxf(d[3] * SCALE, 0.f))};
                *(float2 *)(bufA + Mr * TS + Nc) = lo;
                *(float2 *)(bufA + (Mr + 8) * TS + Nc) = hi;
                s0 += lo.x + hi.x;
                s1 += lo.y + hi.y;
            }
            s0 = shfl_red(s0);
            s1 = shfl_red(s1);
            if (lane < 4) {
                ksp[wr * 128 + Nc] += s0;
                ksp[wr * 128 + Nc + 1] += s1;
            }
        }
        rna_tile(bufV, TSV);              // V scale does NOT cancel -> keep rounded
        __syncthreads();

        wgemm_bn(bufA, bufV, kv);         // kv[m][v] += phi^T V^T (V native)
        __syncthreads();

        if (st + 1 < NSUB) {
            load_tile(sbA, Kbase + (st + 1) * 128, Ll, TS); cpcommit();
            load_tile(sbV, Vbase + (st + 1) * 128, Ll, TSV); cpcommit();
        }
    }

    float *kvp = g_kvpart + (size_t)(b * CH + ch) * 16384;
#pragma unroll
    for (int mt = 0; mt < 2; mt++)
#pragma unroll
        for (int nt = 0; nt < 4; nt++) {
            float *d = kv[mt * 4 + nt];
            int Mr = m0 + mt * 16 + r, Nc = n0 + nt * 8 + 2 * c;
            *(float2 *)(kvp + Mr * 128 + Nc) = make_float2(d[0], d[1]);
            *(float2 *)(kvp + (Mr + 8) * 128 + Nc) = make_float2(d[2], d[3]);
        }
    __syncthreads();
    if (t < 128) g_kspart[(b * CH + ch) * 128 + t] =
        ksp[t] + ksp[128 + t] + ksp[256 + t] + ksp[384 + t];
}

// ---------------- reduce: partials -> kv (rna) + ksum ----------------
__global__ __launch_bounds__(256) void k_red() {
    int mg = blockIdx.x, b = blockIdx.y, t = threadIdx.x;
    int v = (t & 31) * 4, mr = t >> 5;
#pragma unroll
    for (int i = 0; i < 2; i++) {
        int m = mg * 16 + i * 8 + mr;
        float4 a = make_float4(0.f, 0.f, 0.f, 0.f);
#pragma unroll
        for (int ch = 0; ch < CH; ch++) {
            float4 x = *(const float4 *)(g_kvpart + ((size_t)(b * CH + ch) * 128 + m) * 128 + v);
            a.x += x.x; a.y += x.y; a.z += x.z; a.w += x.w;
        }
        a.x = rna(a.x); a.y = rna(a.y); a.z = rna(a.z); a.w = rna(a.w);
        *(float4 *)(g_kv + (size_t)b * 16384 + m * 128 + v) = a;
    }
    if (mg == 0 && t < 128) {
        float s = 0.f;
#pragma unroll
        for (int ch = 0; ch < CH; ch++) s += g_kspart[(b * CH + ch) * 128 + t];
        g_ksum[b * 128 + t] = s;
    }
}

// ---------------- P2: phi_q -> out (4 l-tiles per block) ----------------
// smem: W(persist) | KV(persist) | R(rotating Q->phi) | ks[128] | denp[4][128] | rden[128]
__global__ __launch_bounds__(512, 1) void k_p2(const float *__restrict__ queries,
                                               const float *__restrict__ feats,
                                               float *__restrict__ out) {
    extern __shared__ float sm[];
    float *W = sm, *KV = sm + 128 * TS, *R = sm + 2 * 128 * TS;
    float *ks = sm + 3 * 128 * TS, *denp = ks + 128, *rden = denp + 512;
    uint32_t sb = (uint32_t)__cvta_generic_to_shared(sm);
    uint32_t sbKV = sb + TILE_B, sbR = sb + 2u * TILE_B;
    uint32_t sbKS = sb + 3u * TILE_B;
    int b = blockIdx.y, chunk = blockIdx.x, t = threadIdx.x;
    const float *Qbase = queries + (size_t)b * 128 * Ll + chunk * (TPB2 * 128);

    load_tile(sb, feats, 128, TS);                       // W
    load_tile(sbKV, g_kv + (size_t)b * 16384, 128, TS);  // kv (pre-rounded)
    if (t < 32) cp16(sbKS + (uint32_t)t * 16, g_ksum + b * 128 + t * 4);
    cpcommit();                                          // group A
    load_tile(sbR, Qbase, Ll, TS); cpcommit();           // Q0 (group B)

    int wid = t >> 5, lane = t & 31;
    int m0 = (wid >> 2) * 32, n0 = (wid & 3) * 32;
    int r = lane >> 2, c = lane & 3;
    int wr = wid >> 2;

    for (int tt = 0; tt < TPB2; tt++) {
        int l0 = (chunk * TPB2 + tt) * 128;
        cpwait<0>(); __syncthreads();     // W/kv/ks + Q[tt] ready

        float pa[8][4];
        zero_acc(pa);
        wgemm(W, R, pa);                  // D[m][l] = W^T Q (HW truncates W,Q)
        __syncthreads();                  // Q fully read

        // epilogue: phi -> R[m][l]; denominator fold (den[l] = sum_m phi*ks[m])
#pragma unroll
        for (int nt = 0; nt < 4; nt++) {
            float s0 = 0.f, s1 = 0.f;
            int Nc = n0 + nt * 8 + 2 * c;
#pragma unroll
            for (int mt = 0; mt < 2; mt++) {
                float *d = pa[mt * 4 + nt];
                int Mr = m0 + mt * 16 + r;
                float ka = ks[Mr], kb = ks[Mr + 8];
                float2 lo = {rna(fmaxf(d[0] * SCALE, 0.f)), rna(fmaxf(d[1] * SCALE, 0.f))};
                float2 hi = {rna(fmaxf(d[2] * SCALE, 0.f)), rna(fmaxf(d[3] * SCALE, 0.f))};
                *(float2 *)(R + Mr * TS + Nc) = lo;
                *(float2 *)(R + (Mr + 8) * TS + Nc) = hi;
                s0 = fmaf(lo.x, ka, fmaf(hi.x, kb, s0));
                s1 = fmaf(lo.y, ka, fmaf(hi.y, kb, s1));
            }
            s0 = shfl_red(s0);
            s1 = shfl_red(s1);
            if (lane < 4) {
                denp[wr * 128 + Nc] = s0;
                denp[wr * 128 + Nc + 1] = s1;
            }
        }
        __syncthreads();
        if (t < 128) rden[t] = rcp_nr(denp[t] + denp[128 + t] + denp[256 + t] + denp[384 + t]);

        float oa[8][4];
        zero_acc(oa);
        wgemm(KV, R, oa);                 // D[v][l] = kv^T phi_q
        __syncthreads();                  // R free; rden visible

        if (tt + 1 < TPB2) {              // prefetch next Q while storing
            load_tile(sbR, Qbase + (tt + 1) * 128, Ll, TS); cpcommit();
        }

        // direct store from fragments: out[v][l] = D * rden[l]
#pragma unroll
        for (int nt = 0; nt < 4; nt++) {
            int Nc = n0 + nt * 8 + 2 * c;
            float2 dd = *(float2 *)(rden + Nc);
#pragma unroll
            for (int mt = 0; mt < 2; mt++) {
                float *d = oa[mt * 4 + nt];
                int Mr = m0 + mt * 16 + r;
                *(float2 *)(out + (size_t)(b * 128 + Mr) * Ll + l0 + Nc) =
                    make_float2(d[0] * dd.x, d[1] * dd.y);
                *(float2 *)(out + (size_t)(b * 128 + Mr + 8) * Ll + l0 + Nc) =
                    make_float2(d[2] * dd.x, d[3] * dd.y);
            }
        }
    }
}

// ---------------- launch ----------------
extern "C" void kernel_launch(void *const *d_in, const int *in_sizes, int n_in,
                              void *d_out, int out_size) {
    (void)in_sizes; (void)n_in; (void)out_size;
    const float *keys = (const float *)d_in[0];
    const float *values = (const float *)d_in[1];
    const float *queries = (const float *)d_in[2];
    const float *feats = (const float *)d_in[3];
    float *out = (float *)d_out;

    constexpr int SM_P1 = 2 * TILE_B + TILEV_B + 512 * 4;          // 208896
    constexpr int SM_P2 = 3 * TILE_B + (128 + 512 + 128) * 4;      // 211968

    cudaFuncSetAttribute(k_p1, cudaFuncAttributeMaxDynamicSharedMemorySize, SM_P1);
    cudaFuncSetAttribute(k_p2, cudaFuncAttributeMaxDynamicSharedMemorySize, SM_P2);

    k_p1<<<dim3(CH, Bb), 512, SM_P1>>>(keys, values, feats);
    k_red<<<dim3(8, Bb), 256>>>();
    k_p2<<<dim3(Ll / (TPB2 * 128), Bb), 512, SM_P2>>>(queries, feats, out);
}

// round 15
// speedup vs baseline: 2.5937x; 1.0558x over previous
#include <cuda_runtime.h>
#include <cstdint>
#include <cstddef>

#define DEV static __device__ __forceinline__

constexpr int Bb = 16, Ll = 8192;
constexpr int NBLK = 152;              // flat blocks (= GB300 SM count)
constexpr int NSLOT = NBLK * 2;        // kv partial slots (2 per block)
constexpr int NT = 1024;               // total (batch, l-tile) units: 16*64
constexpr float SCALE = 0.08838834764831845f; // 1/sqrt(128)
constexpr int TS = 136;    // k-major smem tile row stride (floats)
constexpr int TSV = 132;   // n-major (V) smem tile row stride (floats)
constexpr int TILE_B = 128 * TS * 4;   // 69632 bytes
constexpr int TILEV_B = 128 * TSV * 4; // 67584 bytes

// ---------------- scratch (device globals; no allocation) ----------------
__device__ __align__(16) float g_kvpart[(size_t)NSLOT * 16384];
__device__ __align__(16) float g_kspart[NSLOT * 128];
__device__ int g_kvtag[NSLOT];
__device__ __align__(16) float g_kv[Bb * 128 * 128];  // kv: [b][m][v] (tf32-rounded)
__device__ __align__(16) float g_ksum[Bb * 128];

// ---------------- helpers ----------------
DEV float rna(float x) { uint32_t r; asm("cvt.rna.tf32.f32 %0,%1;" : "=r"(r) : "f"(x)); return __uint_as_float(r); }
DEV float rcp_nr(float x) { float r; asm("rcp.approx.f32 %0,%1;" : "=f"(r) : "f"(x)); return r * (2.0f - x * r); }
DEV void cp16(uint32_t s, const void *g) { asm volatile("cp.async.ca.shared.global [%0],[%1],16;" :: "r"(s), "l"(g)); }
DEV void cpcommit() { asm volatile("cp.async.commit_group;"); }
template <int N> DEV void cpwait() { asm volatile("cp.async.wait_group %0;" :: "n"(N)); }

// m16n8k8 tf32 mma (legal on compute_103; runs on the tensor pipe)
DEV void mma8(float *d, const uint32_t *a, const uint32_t *b) {
    asm volatile("mma.sync.aligned.m16n8k8.row.col.f32.tf32.tf32.f32 "
                 "{%0,%1,%2,%3}, {%4,%5,%6,%7}, {%8,%9}, {%0,%1,%2,%3};"
                 : "+f"(d[0]), "+f"(d[1]), "+f"(d[2]), "+f"(d[3])
                 : "r"(a[0]), "r"(a[1]), "r"(a[2]), "r"(a[3]), "r"(b[0]), "r"(b[1]));
}

// Load 128x128 fp32 tile (global row stride gs floats) -> smem rows of stride ss.
// 512 threads, 8 x cp16 each.
DEV void load_tile(uint32_t sb, const float *g, size_t gs, int ss) {
    int t = threadIdx.x, c4 = t & 31, r0 = t >> 5;
#pragma unroll
    for (int i = 0; i < 8; i++) {
        int row = i * 16 + r0;
        cp16(sb + (uint32_t)(row * ss * 4) + (uint32_t)c4 * 16, g + (size_t)row * gs + c4 * 4);
    }
}

// ---------------- 128x128x128 warp-MMA GEMM, 16 warps, warp tile 32x32 ------
// acc(+)= A^T*B ; A k-major [k][m] stride TS, B k-major [k][n] stride TS.
DEV void wgemm(const float *As, const float *Bs, float (*acc)[4]) {
    int t = threadIdx.x, wid = t >> 5, lane = t & 31;
    int m0 = (wid >> 2) * 32, n0 = (wid & 3) * 32;
    int r = lane >> 2, c = lane & 3;
#pragma unroll
    for (int s = 0; s < 16; s++) {
        const float *ak = As + (s * 8 + c) * TS + r;
        const float *bk = Bs + (s * 8 + c) * TS + r;
        uint32_t a[2][4], b[4][2];
#pragma unroll
        for (int mt = 0; mt < 2; mt++) {
            int mo = m0 + mt * 16;
            a[mt][0] = __float_as_uint(ak[mo]);
            a[mt][1] = __float_as_uint(ak[mo + 8]);
            a[mt][2] = __float_as_uint(ak[4 * TS + mo]);
            a[mt][3] = __float_as_uint(ak[4 * TS + mo + 8]);
        }
#pragma unroll
        for (int nt = 0; nt < 4; nt++) {
            int no = n0 + nt * 8;
            b[nt][0] = __float_as_uint(bk[no]);
            b[nt][1] = __float_as_uint(bk[4 * TS + no]);
        }
#pragma unroll
        for (int mt = 0; mt < 2; mt++)
#pragma unroll
            for (int nt = 0; nt < 4; nt++)
                mma8(acc[mt * 4 + nt], a[mt], b[nt]);
    }
}

// Same, but B is n-major [n][k] stride TSV (reads V in its NATIVE layout).
DEV void wgemm_bn(const float *As, const float *Bs, float (*acc)[4]) {
    int t = threadIdx.x, wid = t >> 5, lane = t & 31;
    int m0 = (wid >> 2) * 32, n0 = (wid & 3) * 32;
    int r = lane >> 2, c = lane & 3;
#pragma unroll
    for (int s = 0; s < 16; s++) {
        const float *ak = As + (s * 8 + c) * TS + r;
        uint32_t a[2][4], b[4][2];
#pragma unroll
        for (int mt = 0; mt < 2; mt++) {
            int mo = m0 + mt * 16;
            a[mt][0] = __float_as_uint(ak[mo]);
            a[mt][1] = __float_as_uint(ak[mo + 8]);
            a[mt][2] = __float_as_uint(ak[4 * TS + mo]);
            a[mt][3] = __float_as_uint(ak[4 * TS + mo + 8]);
        }
#pragma unroll
        for (int nt = 0; nt < 4; nt++) {
            const float *bn = Bs + (n0 + nt * 8 + r) * TSV + s * 8 + c;
            b[nt][0] = __float_as_uint(bn[0]);
            b[nt][1] = __float_as_uint(bn[4]);
        }
#pragma unroll
        for (int mt = 0; mt < 2; mt++)
#pragma unroll
            for (int nt = 0; nt < 4; nt++)
                mma8(acc[mt * 4 + nt], a[mt], b[nt]);
    }
}

DEV void zero_acc(float (*a)[4]) {
#pragma unroll
    for (int i = 0; i < 8; i++)
#pragma unroll
        for (int j = 0; j < 4; j++) a[i][j] = 0.f;
}

DEV float shfl_red(float s) {
    s += __shfl_xor_sync(0xffffffffu, s, 4);
    s += __shfl_xor_sync(0xffffffffu, s, 8);
    s += __shfl_xor_sync(0xffffffffu, s, 16);
    return s;
}

// ---------------- P1: phi_k -> kv / ksum partial slots (flat partition) -----
// smem: W(TS) | bufA(TS: K -> phi) | bufV(TSV: V native) | ksp[4][128]
__global__ __launch_bounds__(512, 1) void k_p1(const float *__restrict__ keys,
                                               const float *__restrict__ V,
                                               const float *__restrict__ feats) {
    extern __shared__ float sm[];
    float *W = sm, *bufA = sm + 128 * TS, *bufV = sm + 2 * 128 * TS;
    float *ksp = sm + 2 * 128 * TS + 128 * TSV;
    uint32_t sb = (uint32_t)__cvta_generic_to_shared(sm);
    uint32_t sbA = sb + TILE_B, sbV = sb + 2u * TILE_B;
    int blk = blockIdx.x, t = threadIdx.x;
    int lo = blk * NT / NBLK, hi = (blk + 1) * NT / NBLK;

    auto kptr = [&](int s) { return keys + (size_t)(s >> 6) * 128 * Ll + (s & 63) * 128; };
    auto vptr = [&](int s) { return V + (size_t)(s >> 6) * 128 * Ll + (s & 63) * 128; };

    load_tile(sb, feats, 128, TS);                 // W   (group A)
    load_tile(sbA, kptr(lo), Ll, TS); cpcommit();  // K0  (group A)
    load_tile(sbV, vptr(lo), Ll, TSV); cpcommit(); // V0  (group B)
    ksp[t] = 0.f;

    int wid = t >> 5, lane = t & 31;
    int m0 = (wid >> 2) * 32, n0 = (wid & 3) * 32;
    int r = lane >> 2, c = lane & 3;
    int wr = wid >> 2;

    float kv[8][4];
    zero_acc(kv);
    int seg = 0;

    for (int s = lo; s < hi; s++) {
        cpwait<1>(); __syncthreads();     // K[s] ready (V may be in flight)

        float pa[8][4];
        zero_acc(pa);
        wgemm(bufA, W, pa);               // D[l][m] = K^T W (HW truncates K,W)
        __syncthreads();                  // K tile fully read

        // epilogue: phi = rna(relu(D*scale)) -> bufA[l][m]; ksum fold
#pragma unroll
        for (int nt = 0; nt < 4; nt++) {
            float s0 = 0.f, s1 = 0.f;
            int Nc = n0 + nt * 8 + 2 * c;
#pragma unroll
            for (int mt = 0; mt < 2; mt++) {
                float *d = pa[mt * 4 + nt];
                int Mr = m0 + mt * 16 + r;
                float2 lo2 = {rna(fmaxf(d[0] * SCALE, 0.f)), rna(fmaxf(d[1] * SCALE, 0.f))};
                float2 hi2 = {rna(fmaxf(d[2] * SCALE, 0.f)), rna(fmaxf(d[3] * SCALE, 0.f))};
                *(float2 *)(bufA + Mr * TS + Nc) = lo2;
                *(float2 *)(bufA + (Mr + 8) * TS + Nc) = hi2;
                s0 += lo2.x + hi2.x;
                s1 += lo2.y + hi2.y;
            }
            s0 = shfl_red(s0);
            s1 = shfl_red(s1);
            if (lane < 4) {
                ksp[wr * 128 + Nc] += s0;
                ksp[wr * 128 + Nc + 1] += s1;
            }
        }
        cpwait<0>();                      // V[s] arrived (this thread)
        __syncthreads();                  // phi + V visible to all

        wgemm_bn(bufA, bufV, kv);         // kv[m][v] += phi^T V^T (V truncated by HW)
        __syncthreads();                  // buffers free

        if (s + 1 < hi) {                 // prefetch next subtile
            load_tile(sbA, kptr(s + 1), Ll, TS); cpcommit();
            load_tile(sbV, vptr(s + 1), Ll, TSV); cpcommit();
        }

        bool fl = (s + 1 == hi) || ((s + 1) >> 6) != (s >> 6);
        if (fl) {                         // flush segment partials (<=2 per block)
            int slot = blk * 2 + seg;
            float *kvp = g_kvpart + (size_t)slot * 16384;
#pragma unroll
            for (int mt = 0; mt < 2; mt++)
#pragma unroll
                for (int nt = 0; nt < 4; nt++) {
                    float *d = kv[mt * 4 + nt];
                    int Mr = m0 + mt * 16 + r, Nc = n0 + nt * 8 + 2 * c;
                    *(float2 *)(kvp + Mr * 128 + Nc) = make_float2(d[0], d[1]);
                    *(float2 *)(kvp + (Mr + 8) * 128 + Nc) = make_float2(d[2], d[3]);
                }
            if (t < 128) g_kspart[slot * 128 + t] =
                ksp[t] + ksp[128 + t] + ksp[256 + t] + ksp[384 + t];
            if (t == 0) g_kvtag[slot] = s >> 6;
            __syncthreads();              // ksp reads done before reset
            ksp[t] = 0.f;
            zero_acc(kv);
            seg++;
        }
    }
    if (t == 0)
        for (int q = seg; q < 2; q++) g_kvtag[blk * 2 + q] = -1;
}

// ---------------- reduce: tagged partials -> kv (rna) + ksum ----------------
__global__ __launch_bounds__(256) void k_red() {
    __shared__ int tags[NSLOT];
    int mg = blockIdx.x, b = blockIdx.y, t = threadIdx.x;
    for (int i = t; i < NSLOT; i += 256) tags[i] = g_kvtag[i];
    __syncthreads();

    int v = (t & 31) * 4, mr = t >> 5;
    float4 a0 = make_float4(0.f, 0.f, 0.f, 0.f), a1 = a0;
    int m0_ = mg * 16 + mr, m1_ = mg * 16 + 8 + mr;
    for (int s = 0; s < NSLOT; s++) {
        if (tags[s] != b) continue;
        const float *base = g_kvpart + (size_t)s * 16384;
        float4 x0 = *(const float4 *)(base + m0_ * 128 + v);
        float4 x1 = *(const float4 *)(base + m1_ * 128 + v);
        a0.x += x0.x; a0.y += x0.y; a0.z += x0.z; a0.w += x0.w;
        a1.x += x1.x; a1.y += x1.y; a1.z += x1.z; a1.w += x1.w;
    }
    a0.x = rna(a0.x); a0.y = rna(a0.y); a0.z = rna(a0.z); a0.w = rna(a0.w);
    a1.x = rna(a1.x); a1.y = rna(a1.y); a1.z = rna(a1.z); a1.w = rna(a1.w);
    *(float4 *)(g_kv + (size_t)b * 16384 + m0_ * 128 + v) = a0;
    *(float4 *)(g_kv + (size_t)b * 16384 + m1_ * 128 + v) = a1;

    if (mg == 0 && t < 128) {
        float ss = 0.f;
        for (int s = 0; s < NSLOT; s++)
            if (tags[s] == b) ss += g_kspart[s * 128 + t];
        g_ksum[b * 128 + t] = ss;
    }
}

// ---------------- P2: phi_q -> out (flat partition, W/KV persistent) --------
// smem: W | KV | R (rotating Q->phi) | ks[128] | denp[4][128] | rden[128]
__global__ __launch_bounds__(512, 1) void k_p2(const float *__restrict__ queries,
                                               const float *__restrict__ feats,
                                               float *__restrict__ out) {
    extern __shared__ float sm[];
    float *W = sm, *KV = sm + 128 * TS, *R = sm + 2 * 128 * TS;
    float *ks = sm + 3 * 128 * TS, *denp = ks + 128, *rden = denp + 512;
    uint32_t sb = (uint32_t)__cvta_generic_to_shared(sm);
    uint32_t sbKV = sb + TILE_B, sbR = sb + 2u * TILE_B;
    uint32_t sbKS = sb + 3u * TILE_B;
    int blk = blockIdx.x, t = threadIdx.x;
    int lo = blk * NT / NBLK, hi = (blk + 1) * NT / NBLK;
    int curb = lo >> 6;

    load_tile(sb, feats, 128, TS);                          // W
    load_tile(sbKV, g_kv + (size_t)curb * 16384, 128, TS);  // kv(batch lo)
    if (t < 32) cp16(sbKS + (uint32_t)t * 16, g_ksum + curb * 128 + t * 4);
    cpcommit();
    {   // Q[lo]
        load_tile(sbR, queries + (size_t)(lo >> 6) * 128 * Ll + (lo & 63) * 128, Ll, TS);
        cpcommit();
    }

    int wid = t >> 5, lane = t & 31;
    int m0 = (wid >> 2) * 32, n0 = (wid & 3) * 32;
    int r = lane >> 2, c = lane & 3;
    int wr = wid >> 2;

    for (int tt = lo; tt < hi; tt++) {
        int b = tt >> 6, l0 = (tt & 63) * 128;
        if (b != curb) {                  // <=1 per block: reload kv/ksum
            load_tile(sbKV, g_kv + (size_t)b * 16384, 128, TS);
            if (t < 32) cp16(sbKS + (uint32_t)t * 16, g_ksum + b * 128 + t * 4);
            cpcommit();
            curb = b;
        }
        cpwait<0>(); __syncthreads();     // Q[tt] (+kv/ks) ready

        float pa[8][4];
        zero_acc(pa);
        wgemm(W, R, pa);                  // D[m][l] = W^T Q (HW truncates W,Q)
        __syncthreads();                  // Q fully read

        // epilogue: phi -> R[m][l]; denominator fold (den[l] = sum_m phi*ks[m])
#pragma unroll
        for (int nt = 0; nt < 4; nt++) {
            float s0 = 0.f, s1 = 0.f;
            int Nc = n0 + nt * 8 + 2 * c;
#pragma unroll
            for (int mt = 0; mt < 2; mt++) {
                float *d = pa[mt * 4 + nt];
                int Mr = m0 + mt * 16 + r;
                float ka = ks[Mr], kb = ks[Mr + 8];
                float2 lo2 = {rna(fmaxf(d[0] * SCALE, 0.f)), rna(fmaxf(d[1] * SCALE, 0.f))};
                float2 hi2 = {rna(fmaxf(d[2] * SCALE, 0.f)), rna(fmaxf(d[3] * SCALE, 0.f))};
                *(float2 *)(R + Mr * TS + Nc) = lo2;
                *(float2 *)(R + (Mr + 8) * TS + Nc) = hi2;
                s0 = fmaf(lo2.x, ka, fmaf(hi2.x, kb, s0));
                s1 = fmaf(lo2.y, ka, fmaf(hi2.y, kb, s1));
            }
            s0 = shfl_red(s0);
            s1 = shfl_red(s1);
            if (lane < 4) {
                denp[wr * 128 + Nc] = s0;
                denp[wr * 128 + Nc + 1] = s1;
            }
        }
        __syncthreads();
        if (t < 128) rden[t] = rcp_nr(denp[t] + denp[128 + t] + denp[256 + t] + denp[384 + t]);

        float oa[8][4];
        zero_acc(oa);
        wgemm(KV, R, oa);                 // D[v][l] = kv^T phi_q
        __syncthreads();                  // R free; rden visible

        if (tt + 1 < hi) {                // prefetch next Q while storing
            int nb = (tt + 1) >> 6, nl = ((tt + 1) & 63) * 128;
            load_tile(sbR, queries + (size_t)nb * 128 * Ll + nl, Ll, TS);
            cpcommit();
        }

        // direct store from fragments: out[v][l] = D * rden[l]
#pragma unroll
        for (int nt = 0; nt < 4; nt++) {
            int Nc = n0 + nt * 8 + 2 * c;
            float2 dd = *(float2 *)(rden + Nc);
#pragma unroll
            for (int mt = 0; mt < 2; mt++) {
                float *d = oa[mt * 4 + nt];
                int Mr = m0 + mt * 16 + r;
                *(float2 *)(out + (size_t)(b * 128 + Mr) * Ll + l0 + Nc) =
                    make_float2(d[0] * dd.x, d[1] * dd.y);
                *(float2 *)(out + (size_t)(b * 128 + Mr + 8) * Ll + l0 + Nc) =
                    make_float2(d[2] * dd.x, d[3] * dd.y);
            }
        }
    }
}

// ---------------- launch ----------------
extern "C" void kernel_launch(void *const *d_in, const int *in_sizes, int n_in,
                              void *d_out, int out_size) {
    (void)in_sizes; (void)n_in; (void)out_size;
    const float *keys = (const float *)d_in[0];
    const float *values = (const float *)d_in[1];
    const float *queries = (const float *)d_in[2];
    const float *feats = (const float *)d_in[3];
    float *out = (float *)d_out;

    constexpr int SM_P1 = 2 * TILE_B + TILEV_B + 512 * 4;          // 208896
    constexpr int SM_P2 = 3 * TILE_B + (128 + 512 + 128) * 4;      // 211968

    cudaFuncSetAttribute(k_p1, cudaFuncAttributeMaxDynamicSharedMemorySize, SM_P1);
    cudaFuncSetAttribute(k_p2, cudaFuncAttributeMaxDynamicSharedMemorySize, SM_P2);

    k_p1<<<NBLK, 512, SM_P1>>>(keys, values, feats);
    k_red<<<dim3(8, Bb), 256>>>();
    k_p2<<<NBLK, 512, SM_P2>>>(queries, feats, out);
}